// round 8
// baseline (speedup 1.0000x reference)
#include <cuda_runtime.h>
#include <math.h>
#include <stdint.h>

// Problem: x:(8,4096,512) f32, router_w:(512,8), w1:(8,512,2048), b1:(8,2048),
//          w2:(8,2048,512), b2:(8,512). Output: out (8*4096*512) f32 + aux_loss.
#define NTOK 32768
#define DM   512
#define FF   2048
#define EE   8
#define NK   (NTOK * 2)
#define MAX_TILES 520
#define NKP_MAX (MAX_TILES * 128)
#define RBLK 512
#define RWARPS (RBLK * 8)

// ---------------- device scratch (static, no allocation) ----------------
__device__ float g_H[(size_t)NKP_MAX * FF];       // expert-hidden scratch
__device__ int   g_topk_idx[NK];
__device__ float g_topk_w[NK];
__device__ int   g_cnt[EE];
__device__ int   g_off[EE];
__device__ int   g_cur[EE];
__device__ int   g_top1[EE];
__device__ int   g_list[NKP_MAX];
__device__ float g_wl[NKP_MAX];
__device__ float g_prob_part[RWARPS * EE];
__device__ int   g_tile_e[MAX_TILES];
__device__ int   g_tile_base[MAX_TILES];
__device__ int   g_tile_valid[MAX_TILES];
__device__ int   g_ntiles;

__device__ __forceinline__ uint32_t f2tf32(float f) {
    uint32_t r; asm("cvt.rna.tf32.f32 %0, %1;" : "=r"(r) : "f"(f)); return r;
}
__device__ __forceinline__ void mma_tf32(float* d, const uint32_t* a, const uint32_t* b) {
    asm volatile(
        "mma.sync.aligned.m16n8k8.row.col.f32.tf32.tf32.f32 "
        "{%0,%1,%2,%3}, {%4,%5,%6,%7}, {%8,%9}, {%0,%1,%2,%3};\n"
        : "+f"(d[0]), "+f"(d[1]), "+f"(d[2]), "+f"(d[3])
        : "r"(a[0]), "r"(a[1]), "r"(a[2]), "r"(a[3]), "r"(b[0]), "r"(b[1]));
}
__device__ __forceinline__ float gelu_exact(float v) {
    return 0.5f * v * (1.0f + erff(v * 0.70710678118654752f));
}

// ---------------- zero small state ----------------
__global__ void zero_kernel() {
    int t = threadIdx.x;
    if (t < EE) { g_cnt[t] = 0; g_cur[t] = 0; g_top1[t] = 0; }
}

// ---------------- router ----------------
__global__ __launch_bounds__(256) void router_kernel(
        const float* __restrict__ x, const float* __restrict__ rw) {
    __shared__ float s_rw[EE * DM];
    int tid = threadIdx.x;
    for (int i = tid; i < DM * EE; i += 256) {
        int d = i >> 3, e = i & 7;
        s_rw[e * DM + d] = rw[i];
    }
    __syncthreads();
    int warp = tid >> 5, lane = tid & 31;
    float psum[EE];
#pragma unroll
    for (int e = 0; e < EE; e++) psum[e] = 0.f;
    for (int it = 0; it < 8; it++) {
        int t = blockIdx.x * 64 + warp * 8 + it;
        const float* xr = x + (size_t)t * DM;
        float acc[EE];
#pragma unroll
        for (int e = 0; e < EE; e++) acc[e] = 0.f;
#pragma unroll 4
        for (int j = 0; j < 16; j++) {
            float xv = xr[lane + 32 * j];
#pragma unroll
            for (int e = 0; e < EE; e++) acc[e] += xv * s_rw[e * DM + lane + 32 * j];
        }
#pragma unroll
        for (int e = 0; e < EE; e++) {
#pragma unroll
            for (int o = 16; o > 0; o >>= 1)
                acc[e] += __shfl_down_sync(0xffffffffu, acc[e], o);
        }
        if (lane == 0) {
            int e0 = 0; float v0 = acc[0];
#pragma unroll
            for (int e = 1; e < EE; e++) if (acc[e] > v0) { v0 = acc[e]; e0 = e; }
            int e1 = -1; float v1 = -INFINITY;
#pragma unroll
            for (int e = 0; e < EE; e++)
                if (e != e0 && acc[e] > v1) { v1 = acc[e]; e1 = e; }
            float ex = expf(v1 - v0);
            float inv = 1.f / (1.f + ex);
            g_topk_idx[2 * t] = e0;  g_topk_idx[2 * t + 1] = e1;
            g_topk_w[2 * t] = inv;   g_topk_w[2 * t + 1] = ex * inv;
            atomicAdd(&g_cnt[e0], 1);
            atomicAdd(&g_cnt[e1], 1);
            atomicAdd(&g_top1[e0], 1);
            float s = 0.f; float pe[EE];
#pragma unroll
            for (int e = 0; e < EE; e++) { pe[e] = expf(acc[e] - v0); s += pe[e]; }
            float is = 1.f / s;
#pragma unroll
            for (int e = 0; e < EE; e++) psum[e] += pe[e] * is;
        }
    }
    if (lane == 0) {
        int wg = blockIdx.x * 8 + warp;
#pragma unroll
        for (int e = 0; e < EE; e++) g_prob_part[wg * EE + e] = psum[e];
    }
}

// ---------------- prep: aligned CSR offsets, tile table, aux loss ----------------
__global__ void prep_kernel(float* __restrict__ out, int out_size) {
    __shared__ float s_part[256];
    __shared__ float s_e[EE];
    int t = threadIdx.x;
    int e = t & 7, chunk = t >> 3;
    float s = 0.f;
    int w0 = chunk * 128;
    for (int w = w0; w < w0 + 128; w++) s += g_prob_part[w * EE + e];
    s_part[t] = s;
    __syncthreads();
    if (t < EE) {
        float tot = 0.f;
        for (int c = 0; c < 32; c++) tot += s_part[c * 8 + t];
        s_e[t] = tot;
    }
    __syncthreads();
    if (t == 0) {
        int o = 0, nt = 0;
        for (int ee = 0; ee < EE; ee++) {
            g_off[ee] = o;
            int cnt = g_cnt[ee];
            int ntl = (cnt + 127) >> 7;
            for (int i = 0; i < ntl; i++) {
                g_tile_e[nt] = ee;
                g_tile_base[nt] = o + i * 128;
                int v = cnt - i * 128;
                g_tile_valid[nt] = v > 128 ? 128 : v;
                nt++;
            }
            o += ntl * 128;
        }
        g_ntiles = nt;
        float aux = 0.f;
        const float invN = 1.f / (float)NTOK;
        for (int ee = 0; ee < EE; ee++)
            aux += (s_e[ee] * invN) * ((float)g_top1[ee] * invN);
        aux *= 0.01f * (float)EE;
        if (out_size > NTOK * DM) out[(size_t)NTOK * DM] = aux;
    }
}

// ---------------- fused scatter + pad (disjoint slot ranges) ----------------
__global__ void scatter_pad_kernel() {
    int b = blockIdx.x;
    if (b < NTOK / 256) {
        int t = b * 256 + threadIdx.x;
#pragma unroll
        for (int k = 0; k < 2; k++) {
            int e = g_topk_idx[2 * t + k];
            int p = atomicAdd(&g_cur[e], 1);
            int s = g_off[e] + p;
            g_list[s] = t;
            g_wl[s] = g_topk_w[2 * t + k];
        }
    } else {
        int s = (b - NTOK / 256) * 256 + threadIdx.x;
        if (s >= NKP_MAX) return;
        int e = EE - 1;
        for (int i = 1; i < EE; i++) if (s < g_off[i]) { e = i - 1; break; }
        if (s >= g_off[e] + g_cnt[e]) { g_list[s] = 0; g_wl[s] = 0.f; }
    }
}

// ---------------- tf32 warp-MMA grouped GEMM ----------------
// CTA tile 128x256, BK=32, 256 threads = 8 warps (2x4), warp tile 64x64.
// Dynamic SMEM: A [2][32][136], B [2][32][264]; one __syncthreads per K=32.
#define ASTR 136
#define BSTR 264
#define A_ST (32 * ASTR)            // floats per A stage
#define B_ST (32 * BSTR)            // floats per B stage
#define SMEM_FLOATS (2 * A_ST + 2 * B_ST)
#define SMEM_BYTES  (SMEM_FLOATS * 4)

template<int PHASE>
__global__ __launch_bounds__(256, 1) void moe_mma(
        const float* __restrict__ x,
        const float* __restrict__ wmat,
        const float* __restrict__ bias_all,
        float* __restrict__ out) {
    constexpr int KD  = (PHASE == 1) ? DM : FF;   // reduction dim
    constexpr int ND  = (PHASE == 1) ? FF : DM;   // output dim (B row stride)
    constexpr int NIT = KD / 32;

    int tile = blockIdx.y;
    if (tile >= g_ntiles) return;
    int e     = g_tile_e[tile];
    int base  = g_tile_base[tile];
    int valid = g_tile_valid[tile];
    int nb    = blockIdx.x * 256;

    extern __shared__ float sm[];
    float* Abase = sm;
    float* Bbase = sm + 2 * A_ST;

    int t = threadIdx.x;
    int wid = t >> 5, lane = t & 31;
    int g  = lane >> 2;          // 0..7
    int tg = lane & 3;           // 0..3
    int warp_m = (wid >> 2) * 64;
    int warp_n = (wid & 3) * 64;

    // A loader: row r = t&127, k-offsets kq and kq+16 (kq = (t>>7)*8)
    int r  = t & 127;
    int kq = (t >> 7) * 8;
    const float* arow;
    if (PHASE == 1) {
        int tok = g_list[base + r];
        arow = x + (size_t)tok * DM;
    } else {
        arow = g_H + (size_t)(base + r) * FF;
    }
    // B loader: k-rows kr and kr+16 (kr = t>>4); cols bn8 and bn8+128
    int kr  = t >> 4;
    int bn8 = (t & 15) * 8;
    const float* Bsrc = wmat + (size_t)e * KD * ND + nb;  // [k][n], row stride ND

    float acc[4][8][4];
#pragma unroll
    for (int mt = 0; mt < 4; mt++)
#pragma unroll
        for (int nt = 0; nt < 8; nt++)
#pragma unroll
            for (int i = 0; i < 4; i++) acc[mt][nt][i] = 0.f;

    // ---- prolog: fill stage 0 (kb = 0) ----
    {
        float la[16], lb[32];
        *(float4*)&la[0]  = *(const float4*)(arow + kq);
        *(float4*)&la[4]  = *(const float4*)(arow + kq + 4);
        *(float4*)&la[8]  = *(const float4*)(arow + kq + 16);
        *(float4*)&la[12] = *(const float4*)(arow + kq + 20);
        const float* bp0 = Bsrc + (size_t)kr * ND + bn8;
        const float* bp1 = Bsrc + (size_t)(kr + 16) * ND + bn8;
        *(float4*)&lb[0]  = *(const float4*)(bp0);
        *(float4*)&lb[4]  = *(const float4*)(bp0 + 4);
        *(float4*)&lb[8]  = *(const float4*)(bp0 + 128);
        *(float4*)&lb[12] = *(const float4*)(bp0 + 132);
        *(float4*)&lb[16] = *(const float4*)(bp1);
        *(float4*)&lb[20] = *(const float4*)(bp1 + 4);
        *(float4*)&lb[24] = *(const float4*)(bp1 + 128);
        *(float4*)&lb[28] = *(const float4*)(bp1 + 132);
#pragma unroll
        for (int j = 0; j < 8; j++) {
            Abase[(kq + j) * ASTR + r]      = __uint_as_float(f2tf32(la[j]));
            Abase[(kq + 16 + j) * ASTR + r] = __uint_as_float(f2tf32(la[8 + j]));
        }
        float* Br0 = Bbase + kr * BSTR + bn8;
        float* Br1 = Bbase + (kr + 16) * BSTR + bn8;
        *(uint4*)(Br0)       = make_uint4(f2tf32(lb[0]),  f2tf32(lb[1]),  f2tf32(lb[2]),  f2tf32(lb[3]));
        *(uint4*)(Br0 + 4)   = make_uint4(f2tf32(lb[4]),  f2tf32(lb[5]),  f2tf32(lb[6]),  f2tf32(lb[7]));
        *(uint4*)(Br0 + 128) = make_uint4(f2tf32(lb[8]),  f2tf32(lb[9]),  f2tf32(lb[10]), f2tf32(lb[11]));
        *(uint4*)(Br0 + 132) = make_uint4(f2tf32(lb[12]), f2tf32(lb[13]), f2tf32(lb[14]), f2tf32(lb[15]));
        *(uint4*)(Br1)       = make_uint4(f2tf32(lb[16]), f2tf32(lb[17]), f2tf32(lb[18]), f2tf32(lb[19]));
        *(uint4*)(Br1 + 4)   = make_uint4(f2tf32(lb[20]), f2tf32(lb[21]), f2tf32(lb[22]), f2tf32(lb[23]));
        *(uint4*)(Br1 + 128) = make_uint4(f2tf32(lb[24]), f2tf32(lb[25]), f2tf32(lb[26]), f2tf32(lb[27]));
        *(uint4*)(Br1 + 132) = make_uint4(f2tf32(lb[28]), f2tf32(lb[29]), f2tf32(lb[30]), f2tf32(lb[31]));
        __syncthreads();
    }

    for (int it = 0; it < NIT; it++) {
        int s = it & 1, sn = s ^ 1;
        bool more = (it + 1 < NIT);
        const float* As = Abase + s * A_ST;
        const float* Bs = Bbase + s * B_ST;
        int kb = (it + 1) * 32;

        // prefetch next A
        float la[16];
        if (more) {
            *(float4*)&la[0]  = *(const float4*)(arow + kb + kq);
            *(float4*)&la[4]  = *(const float4*)(arow + kb + kq + 4);
            *(float4*)&la[8]  = *(const float4*)(arow + kb + kq + 16);
            *(float4*)&la[12] = *(const float4*)(arow + kb + kq + 20);
        }
        // compute ks = 0,1
#pragma unroll
        for (int ks = 0; ks < 2; ks++) {
            int krow = ks * 8 + tg;
            uint32_t af[4][4], bf[8][2];
#pragma unroll
            for (int mt = 0; mt < 4; mt++) {
                int m0 = warp_m + mt * 16 + g;
                af[mt][0] = __float_as_uint(As[krow * ASTR + m0]);
                af[mt][1] = __float_as_uint(As[krow * ASTR + m0 + 8]);
                af[mt][2] = __float_as_uint(As[(krow + 4) * ASTR + m0]);
                af[mt][3] = __float_as_uint(As[(krow + 4) * ASTR + m0 + 8]);
            }
#pragma unroll
            for (int nt = 0; nt < 8; nt++) {
                int n0 = warp_n + nt * 8 + g;
                bf[nt][0] = __float_as_uint(Bs[krow * BSTR + n0]);
                bf[nt][1] = __float_as_uint(Bs[(krow + 4) * BSTR + n0]);
            }
#pragma unroll
            for (int mt = 0; mt < 4; mt++)
#pragma unroll
                for (int nt = 0; nt < 8; nt++)
                    mma_tf32(acc[mt][nt], af[mt], bf[nt]);
        }
        // store next A, prefetch next B
        float lb[32];
        if (more) {
            float* Asn = Abase + sn * A_ST;
#pragma unroll
            for (int j = 0; j < 8; j++) {
                Asn[(kq + j) * ASTR + r]      = __uint_as_float(f2tf32(la[j]));
                Asn[(kq + 16 + j) * ASTR + r] = __uint_as_float(f2tf32(la[8 + j]));
            }
            const float* bp0 = Bsrc + (size_t)(kb + kr) * ND + bn8;
            const float* bp1 = Bsrc + (size_t)(kb + kr + 16) * ND + bn8;
            *(float4*)&lb[0]  = *(const float4*)(bp0);
            *(float4*)&lb[4]  = *(const float4*)(bp0 + 4);
            *(float4*)&lb[8]  = *(const float4*)(bp0 + 128);
            *(float4*)&lb[12] = *(const float4*)(bp0 + 132);
            *(float4*)&lb[16] = *(const float4*)(bp1);
            *(float4*)&lb[20] = *(const float4*)(bp1 + 4);
            *(float4*)&lb[24] = *(const float4*)(bp1 + 128);
            *(float4*)&lb[28] = *(const float4*)(bp1 + 132);
        }
        // compute ks = 2,3
#pragma unroll
        for (int ks = 2; ks < 4; ks++) {
            int krow = ks * 8 + tg;
            uint32_t af[4][4], bf[8][2];
#pragma unroll
            for (int mt = 0; mt < 4; mt++) {
                int m0 = warp_m + mt * 16 + g;
                af[mt][0] = __float_as_uint(As[krow * ASTR + m0]);
                af[mt][1] = __float_as_uint(As[krow * ASTR + m0 + 8]);
                af[mt][2] = __float_as_uint(As[(krow + 4) * ASTR + m0]);
                af[mt][3] = __float_as_uint(As[(krow + 4) * ASTR + m0 + 8]);
            }
#pragma unroll
            for (int nt = 0; nt < 8; nt++) {
                int n0 = warp_n + nt * 8 + g;
                bf[nt][0] = __float_as_uint(Bs[krow * BSTR + n0]);
                bf[nt][1] = __float_as_uint(Bs[(krow + 4) * BSTR + n0]);
            }
#pragma unroll
            for (int mt = 0; mt < 4; mt++)
#pragma unroll
                for (int nt = 0; nt < 8; nt++)
                    mma_tf32(acc[mt][nt], af[mt], bf[nt]);
        }
        // store next B, advance
        if (more) {
            float* Br0 = Bbase + sn * B_ST + kr * BSTR + bn8;
            float* Br1 = Bbase + sn * B_ST + (kr + 16) * BSTR + bn8;
            *(uint4*)(Br0)       = make_uint4(f2tf32(lb[0]),  f2tf32(lb[1]),  f2tf32(lb[2]),  f2tf32(lb[3]));
            *(uint4*)(Br0 + 4)   = make_uint4(f2tf32(lb[4]),  f2tf32(lb[5]),  f2tf32(lb[6]),  f2tf32(lb[7]));
            *(uint4*)(Br0 + 128) = make_uint4(f2tf32(lb[8]),  f2tf32(lb[9]),  f2tf32(lb[10]), f2tf32(lb[11]));
            *(uint4*)(Br0 + 132) = make_uint4(f2tf32(lb[12]), f2tf32(lb[13]), f2tf32(lb[14]), f2tf32(lb[15]));
            *(uint4*)(Br1)       = make_uint4(f2tf32(lb[16]), f2tf32(lb[17]), f2tf32(lb[18]), f2tf32(lb[19]));
            *(uint4*)(Br1 + 4)   = make_uint4(f2tf32(lb[20]), f2tf32(lb[21]), f2tf32(lb[22]), f2tf32(lb[23]));
            *(uint4*)(Br1 + 128) = make_uint4(f2tf32(lb[24]), f2tf32(lb[25]), f2tf32(lb[26]), f2tf32(lb[27]));
            *(uint4*)(Br1 + 132) = make_uint4(f2tf32(lb[28]), f2tf32(lb[29]), f2tf32(lb[30]), f2tf32(lb[31]));
            __syncthreads();
        }
    }

    // ---------------- epilogue ----------------
    // Fragment D mapping: c0:(row=g, col=tg*2) c1:(col+1) c2:(row+8) c3:(row+8,col+1)
    const float* bvec = bias_all + (size_t)e * ND + nb;
    if (PHASE == 1) {
#pragma unroll
        for (int mt = 0; mt < 4; mt++) {
            int rr0 = warp_m + mt * 16 + g;
            float* H0 = g_H + (size_t)(base + rr0) * FF + nb;
            float* H1 = g_H + (size_t)(base + rr0 + 8) * FF + nb;
#pragma unroll
            for (int nt = 0; nt < 8; nt++) {
                int c = warp_n + nt * 8 + tg * 2;
                float b0 = bvec[c], b1 = bvec[c + 1];
                float2 v0, v1;
                v0.x = gelu_exact(acc[mt][nt][0] + b0);
                v0.y = gelu_exact(acc[mt][nt][1] + b1);
                v1.x = gelu_exact(acc[mt][nt][2] + b0);
                v1.y = gelu_exact(acc[mt][nt][3] + b1);
                *(float2*)(H0 + c) = v0;
                *(float2*)(H1 + c) = v1;
            }
        }
    } else {
#pragma unroll
        for (int mt = 0; mt < 4; mt++) {
            int rr0 = warp_m + mt * 16 + g;
#pragma unroll
            for (int half = 0; half < 2; half++) {
                int rr = rr0 + half * 8;
                if (rr < valid) {
                    int slot = base + rr;
                    int tok  = g_list[slot];
                    float gw = g_wl[slot];
                    float* O = out + (size_t)tok * DM + nb;
#pragma unroll
                    for (int nt = 0; nt < 8; nt++) {
                        int c = warp_n + nt * 8 + tg * 2;
                        atomicAdd(O + c,     gw * (acc[mt][nt][half * 2]     + bvec[c]));
                        atomicAdd(O + c + 1, gw * (acc[mt][nt][half * 2 + 1] + bvec[c + 1]));
                    }
                }
            }
        }
    }
}

// ---------------- launch ----------------
extern "C" void kernel_launch(void* const* d_in, const int* in_sizes, int n_in,
                              void* d_out, int out_size) {
    const float* x  = (const float*)d_in[0];
    const float* rw = (const float*)d_in[1];
    const float* w1 = (const float*)d_in[2];
    const float* b1 = (const float*)d_in[3];
    const float* w2 = (const float*)d_in[4];
    const float* b2 = (const float*)d_in[5];
    float* out = (float*)d_out;

    cudaFuncSetAttribute(moe_mma<1>, cudaFuncAttributeMaxDynamicSharedMemorySize, SMEM_BYTES);
    cudaFuncSetAttribute(moe_mma<2>, cudaFuncAttributeMaxDynamicSharedMemorySize, SMEM_BYTES);

    // Order chosen so the ncu capture slot (fixed -s) lands on moe_mma<1>.
    zero_kernel<<<1, 32>>>();
    router_kernel<<<RBLK, 256>>>(x, rw);
    prep_kernel<<<1, 256>>>(out, out_size);
    scatter_pad_kernel<<<NTOK / 256 + NKP_MAX / 256, 256>>>();
    moe_mma<1><<<dim3(FF / 256, MAX_TILES), 256, SMEM_BYTES>>>(x, w1, b1, nullptr);
    cudaMemsetAsync(out, 0, (size_t)NTOK * DM * sizeof(float), 0);  // zero before gemm2 atomics; aux at [NTOK*DM] untouched
    moe_mma<2><<<dim3(DM / 256, MAX_TILES), 256, SMEM_BYTES>>>(x, w2, b2, out);
}

// round 9
// speedup vs baseline: 1.0485x; 1.0485x over previous
#include <cuda_runtime.h>
#include <math.h>
#include <stdint.h>

// Problem: x:(8,4096,512) f32, router_w:(512,8), w1:(8,512,2048), b1:(8,2048),
//          w2:(8,2048,512), b2:(8,512). Output: out (8*4096*512) f32 + aux_loss.
#define NTOK 32768
#define DM   512
#define FF   2048
#define EE   8
#define NK   (NTOK * 2)
#define MAX_TILES 520
#define NKP_MAX (MAX_TILES * 128)
#define RBLK 512
#define RWARPS (RBLK * 8)

// ---------------- device scratch (static, no allocation) ----------------
__device__ float g_H[(size_t)NKP_MAX * FF];       // expert-hidden scratch
__device__ int   g_topk_idx[NK];
__device__ float g_topk_w[NK];
__device__ int   g_cnt[EE];
__device__ int   g_off[EE];
__device__ int   g_cur[EE];
__device__ int   g_top1[EE];
__device__ int   g_list[NKP_MAX];
__device__ float g_wl[NKP_MAX];
__device__ float g_prob_part[RWARPS * EE];
__device__ int   g_tile_e[MAX_TILES];
__device__ int   g_tile_base[MAX_TILES];
__device__ int   g_tile_valid[MAX_TILES];
__device__ int   g_ntiles;

__device__ __forceinline__ uint32_t f2tf32(float f) {
    uint32_t r; asm("cvt.rna.tf32.f32 %0, %1;" : "=r"(r) : "f"(f)); return r;
}
__device__ __forceinline__ void mma_tf32(float* d, const uint32_t* a, const uint32_t* b) {
    asm volatile(
        "mma.sync.aligned.m16n8k8.row.col.f32.tf32.tf32.f32 "
        "{%0,%1,%2,%3}, {%4,%5,%6,%7}, {%8,%9}, {%0,%1,%2,%3};\n"
        : "+f"(d[0]), "+f"(d[1]), "+f"(d[2]), "+f"(d[3])
        : "r"(a[0]), "r"(a[1]), "r"(a[2]), "r"(a[3]), "r"(b[0]), "r"(b[1]));
}
__device__ __forceinline__ void red_add_v2(float* addr, float a, float b) {
    asm volatile("red.global.add.v2.f32 [%0], {%1, %2};"
                 :: "l"(addr), "f"(a), "f"(b) : "memory");
}
__device__ __forceinline__ float gelu_exact(float v) {
    return 0.5f * v * (1.0f + erff(v * 0.70710678118654752f));
}

// ---------------- zero small state ----------------
__global__ void zero_kernel() {
    int t = threadIdx.x;
    if (t < EE) { g_cnt[t] = 0; g_cur[t] = 0; g_top1[t] = 0; }
}

// ---------------- router ----------------
__global__ __launch_bounds__(256) void router_kernel(
        const float* __restrict__ x, const float* __restrict__ rw) {
    __shared__ float s_rw[EE * DM];
    int tid = threadIdx.x;
    for (int i = tid; i < DM * EE; i += 256) {
        int d = i >> 3, e = i & 7;
        s_rw[e * DM + d] = rw[i];
    }
    __syncthreads();
    int warp = tid >> 5, lane = tid & 31;
    float psum[EE];
#pragma unroll
    for (int e = 0; e < EE; e++) psum[e] = 0.f;
    for (int it = 0; it < 8; it++) {
        int t = blockIdx.x * 64 + warp * 8 + it;
        const float* xr = x + (size_t)t * DM;
        float acc[EE];
#pragma unroll
        for (int e = 0; e < EE; e++) acc[e] = 0.f;
#pragma unroll 4
        for (int j = 0; j < 16; j++) {
            float xv = xr[lane + 32 * j];
#pragma unroll
            for (int e = 0; e < EE; e++) acc[e] += xv * s_rw[e * DM + lane + 32 * j];
        }
#pragma unroll
        for (int e = 0; e < EE; e++) {
#pragma unroll
            for (int o = 16; o > 0; o >>= 1)
                acc[e] += __shfl_down_sync(0xffffffffu, acc[e], o);
        }
        if (lane == 0) {
            int e0 = 0; float v0 = acc[0];
#pragma unroll
            for (int e = 1; e < EE; e++) if (acc[e] > v0) { v0 = acc[e]; e0 = e; }
            int e1 = -1; float v1 = -INFINITY;
#pragma unroll
            for (int e = 0; e < EE; e++)
                if (e != e0 && acc[e] > v1) { v1 = acc[e]; e1 = e; }
            float ex = expf(v1 - v0);
            float inv = 1.f / (1.f + ex);
            g_topk_idx[2 * t] = e0;  g_topk_idx[2 * t + 1] = e1;
            g_topk_w[2 * t] = inv;   g_topk_w[2 * t + 1] = ex * inv;
            atomicAdd(&g_cnt[e0], 1);
            atomicAdd(&g_cnt[e1], 1);
            atomicAdd(&g_top1[e0], 1);
            float s = 0.f; float pe[EE];
#pragma unroll
            for (int e = 0; e < EE; e++) { pe[e] = expf(acc[e] - v0); s += pe[e]; }
            float is = 1.f / s;
#pragma unroll
            for (int e = 0; e < EE; e++) psum[e] += pe[e] * is;
        }
    }
    if (lane == 0) {
        int wg = blockIdx.x * 8 + warp;
#pragma unroll
        for (int e = 0; e < EE; e++) g_prob_part[wg * EE + e] = psum[e];
    }
}

// ---------------- prep: aligned CSR offsets, tile table, aux loss ----------------
__global__ void prep_kernel(float* __restrict__ out, int out_size) {
    __shared__ float s_part[256];
    __shared__ float s_e[EE];
    int t = threadIdx.x;
    int e = t & 7, chunk = t >> 3;
    float s = 0.f;
    int w0 = chunk * 128;
    for (int w = w0; w < w0 + 128; w++) s += g_prob_part[w * EE + e];
    s_part[t] = s;
    __syncthreads();
    if (t < EE) {
        float tot = 0.f;
        for (int c = 0; c < 32; c++) tot += s_part[c * 8 + t];
        s_e[t] = tot;
    }
    __syncthreads();
    if (t == 0) {
        int o = 0, nt = 0;
        for (int ee = 0; ee < EE; ee++) {
            g_off[ee] = o;
            int cnt = g_cnt[ee];
            int ntl = (cnt + 127) >> 7;
            for (int i = 0; i < ntl; i++) {
                g_tile_e[nt] = ee;
                g_tile_base[nt] = o + i * 128;
                int v = cnt - i * 128;
                g_tile_valid[nt] = v > 128 ? 128 : v;
                nt++;
            }
            o += ntl * 128;
        }
        g_ntiles = nt;
        float aux = 0.f;
        const float invN = 1.f / (float)NTOK;
        for (int ee = 0; ee < EE; ee++)
            aux += (s_e[ee] * invN) * ((float)g_top1[ee] * invN);
        aux *= 0.01f * (float)EE;
        if (out_size > NTOK * DM) out[(size_t)NTOK * DM] = aux;
    }
}

// ---------------- fused scatter + pad (disjoint slot ranges) ----------------
__global__ void scatter_pad_kernel() {
    int b = blockIdx.x;
    if (b < NTOK / 256) {
        int t = b * 256 + threadIdx.x;
#pragma unroll
        for (int k = 0; k < 2; k++) {
            int e = g_topk_idx[2 * t + k];
            int p = atomicAdd(&g_cur[e], 1);
            int s = g_off[e] + p;
            g_list[s] = t;
            g_wl[s] = g_topk_w[2 * t + k];
        }
    } else {
        int s = (b - NTOK / 256) * 256 + threadIdx.x;
        if (s >= NKP_MAX) return;
        int e = EE - 1;
        for (int i = 1; i < EE; i++) if (s < g_off[i]) { e = i - 1; break; }
        if (s >= g_off[e] + g_cnt[e]) { g_list[s] = 0; g_wl[s] = 0.f; }
    }
}

// ---------------- tf32 warp-MMA grouped GEMM ----------------
// CTA tile 128x256, BK=16, 256 threads = 8 warps (2x4), warp tile 64x64.
// Dynamic SMEM: A [2][16][136], B [2][16][264] (strides keep LDS conflict-free).
#define ASTR 136
#define BSTR 264
#define A_ST (16 * ASTR)            // floats per A stage
#define B_ST (16 * BSTR)            // floats per B stage
#define SMEM_FLOATS (2 * A_ST + 2 * B_ST)
#define SMEM_BYTES  (SMEM_FLOATS * 4)

template<int PHASE>
__global__ __launch_bounds__(256, 1) void moe_mma(
        const float* __restrict__ x,
        const float* __restrict__ wmat,
        const float* __restrict__ bias_all,
        float* __restrict__ out) {
    constexpr int KD  = (PHASE == 1) ? DM : FF;   // reduction dim
    constexpr int ND  = (PHASE == 1) ? FF : DM;   // output dim (B row stride)
    constexpr int NIT = KD / 16;

    int tile = blockIdx.y;
    if (tile >= g_ntiles) return;
    int e     = g_tile_e[tile];
    int base  = g_tile_base[tile];
    int valid = g_tile_valid[tile];
    int nb    = blockIdx.x * 256;

    extern __shared__ float sm[];
    // As[s][k][m] = sm[s*A_ST + k*ASTR + m]
    // Bs[s][k][n] = sm[2*A_ST + s*B_ST + k*BSTR + n]
    float* Abase = sm;
    float* Bbase = sm + 2 * A_ST;

    int t = threadIdx.x;
    int wid = t >> 5, lane = t & 31;
    int g  = lane >> 2;          // 0..7
    int tg = lane & 3;           // 0..3
    int warp_m = (wid >> 2) * 64;
    int warp_n = (wid & 3) * 64;

    // A loader: row r = t&127, k-half kq = (t>>7)*8
    int r  = t & 127;
    int kq = (t >> 7) * 8;
    const float* arow;
    if (PHASE == 1) {
        int tok = g_list[base + r];
        arow = x + (size_t)tok * DM;
    } else {
        arow = g_H + (size_t)(base + r) * FF;
    }
    // B loader: k-row kr = t>>4, col block bn8 = (t&15)*8, two halves (+0, +128)
    int kr  = t >> 4;
    int bn8 = (t & 15) * 8;
    const float* Bsrc = wmat + (size_t)e * KD * ND + nb;  // [k][n], row stride ND

    float acc[4][8][4];
#pragma unroll
    for (int mt = 0; mt < 4; mt++)
#pragma unroll
        for (int nt = 0; nt < 8; nt++)
#pragma unroll
            for (int i = 0; i < 4; i++) acc[mt][nt][i] = 0.f;

    // ---- prolog: stage 0 ----
    {
        float la[8], lb0[8], lb1[8];
        *(float4*)&la[0] = *(const float4*)(arow + kq);
        *(float4*)&la[4] = *(const float4*)(arow + kq + 4);
        const float* bp = Bsrc + (size_t)kr * ND + bn8;
        *(float4*)&lb0[0] = *(const float4*)(bp);
        *(float4*)&lb0[4] = *(const float4*)(bp + 4);
        *(float4*)&lb1[0] = *(const float4*)(bp + 128);
        *(float4*)&lb1[4] = *(const float4*)(bp + 132);
        float* As0 = Abase;
#pragma unroll
        for (int j = 0; j < 8; j++)
            As0[(kq + j) * ASTR + r] = __uint_as_float(f2tf32(la[j]));
        float* Brow = Bbase + kr * BSTR + bn8;
        *(uint4*)(Brow)       = make_uint4(f2tf32(lb0[0]), f2tf32(lb0[1]), f2tf32(lb0[2]), f2tf32(lb0[3]));
        *(uint4*)(Brow + 4)   = make_uint4(f2tf32(lb0[4]), f2tf32(lb0[5]), f2tf32(lb0[6]), f2tf32(lb0[7]));
        *(uint4*)(Brow + 128) = make_uint4(f2tf32(lb1[0]), f2tf32(lb1[1]), f2tf32(lb1[2]), f2tf32(lb1[3]));
        *(uint4*)(Brow + 132) = make_uint4(f2tf32(lb1[4]), f2tf32(lb1[5]), f2tf32(lb1[6]), f2tf32(lb1[7]));
        __syncthreads();
    }

    for (int it = 0; it < NIT; it++) {
        int s = it & 1;
        bool more = (it + 1 < NIT);
        float la[8], lb0[8], lb1[8];
        if (more) {
            int kb = (it + 1) * 16;
            *(float4*)&la[0] = *(const float4*)(arow + kb + kq);
            *(float4*)&la[4] = *(const float4*)(arow + kb + kq + 4);
            const float* bp = Bsrc + (size_t)(kb + kr) * ND + bn8;
            *(float4*)&lb0[0] = *(const float4*)(bp);
            *(float4*)&lb0[4] = *(const float4*)(bp + 4);
            *(float4*)&lb1[0] = *(const float4*)(bp + 128);
            *(float4*)&lb1[4] = *(const float4*)(bp + 132);
        }
        const float* As = Abase + s * A_ST;
        const float* Bs = Bbase + s * B_ST;
        // ---- compute 2 k8-steps from stage s ----
#pragma unroll
        for (int ks = 0; ks < 2; ks++) {
            int krow = ks * 8 + tg;
            uint32_t af[4][4], bf[8][2];
#pragma unroll
            for (int mt = 0; mt < 4; mt++) {
                int m0 = warp_m + mt * 16 + g;
                af[mt][0] = __float_as_uint(As[krow * ASTR + m0]);
                af[mt][1] = __float_as_uint(As[krow * ASTR + m0 + 8]);
                af[mt][2] = __float_as_uint(As[(krow + 4) * ASTR + m0]);
                af[mt][3] = __float_as_uint(As[(krow + 4) * ASTR + m0 + 8]);
            }
#pragma unroll
            for (int nt = 0; nt < 8; nt++) {
                int n0 = warp_n + nt * 8 + g;
                bf[nt][0] = __float_as_uint(Bs[krow * BSTR + n0]);
                bf[nt][1] = __float_as_uint(Bs[(krow + 4) * BSTR + n0]);
            }
#pragma unroll
            for (int mt = 0; mt < 4; mt++)
#pragma unroll
                for (int nt = 0; nt < 8; nt++)
                    mma_tf32(acc[mt][nt], af[mt], bf[nt]);
        }
        if (more) {
            int sn = s ^ 1;
            float* Asn = Abase + sn * A_ST;
#pragma unroll
            for (int j = 0; j < 8; j++)
                Asn[(kq + j) * ASTR + r] = __uint_as_float(f2tf32(la[j]));
            float* Brow = Bbase + sn * B_ST + kr * BSTR + bn8;
            *(uint4*)(Brow)       = make_uint4(f2tf32(lb0[0]), f2tf32(lb0[1]), f2tf32(lb0[2]), f2tf32(lb0[3]));
            *(uint4*)(Brow + 4)   = make_uint4(f2tf32(lb0[4]), f2tf32(lb0[5]), f2tf32(lb0[6]), f2tf32(lb0[7]));
            *(uint4*)(Brow + 128) = make_uint4(f2tf32(lb1[0]), f2tf32(lb1[1]), f2tf32(lb1[2]), f2tf32(lb1[3]));
            *(uint4*)(Brow + 132) = make_uint4(f2tf32(lb1[4]), f2tf32(lb1[5]), f2tf32(lb1[6]), f2tf32(lb1[7]));
            __syncthreads();
        }
    }

    // ---------------- epilogue ----------------
    // Fragment D mapping: c0:(row=g, col=tg*2) c1:(col+1) c2:(row+8) c3:(row+8,col+1)
    const float* bvec = bias_all + (size_t)e * ND + nb;
    if (PHASE == 1) {
#pragma unroll
        for (int mt = 0; mt < 4; mt++) {
            int rr0 = warp_m + mt * 16 + g;
            float* H0 = g_H + (size_t)(base + rr0) * FF + nb;
            float* H1 = g_H + (size_t)(base + rr0 + 8) * FF + nb;
#pragma unroll
            for (int nt = 0; nt < 8; nt++) {
                int c = warp_n + nt * 8 + tg * 2;
                float b0 = bvec[c], b1 = bvec[c + 1];
                float2 v0, v1;
                v0.x = gelu_exact(acc[mt][nt][0] + b0);
                v0.y = gelu_exact(acc[mt][nt][1] + b1);
                v1.x = gelu_exact(acc[mt][nt][2] + b0);
                v1.y = gelu_exact(acc[mt][nt][3] + b1);
                *(float2*)(H0 + c) = v0;
                *(float2*)(H1 + c) = v1;
            }
        }
    } else {
#pragma unroll
        for (int mt = 0; mt < 4; mt++) {
            int rr0 = warp_m + mt * 16 + g;
#pragma unroll
            for (int half = 0; half < 2; half++) {
                int rr = rr0 + half * 8;
                if (rr < valid) {
                    int slot = base + rr;
                    int tok  = g_list[slot];
                    float gw = g_wl[slot];
                    float* O = out + (size_t)tok * DM + nb;
#pragma unroll
                    for (int nt = 0; nt < 8; nt++) {
                        int c = warp_n + nt * 8 + tg * 2;
                        red_add_v2(O + c,
                                   gw * (acc[mt][nt][half * 2]     + bvec[c]),
                                   gw * (acc[mt][nt][half * 2 + 1] + bvec[c + 1]));
                    }
                }
            }
        }
    }
}

// ---------------- launch ----------------
extern "C" void kernel_launch(void* const* d_in, const int* in_sizes, int n_in,
                              void* d_out, int out_size) {
    const float* x  = (const float*)d_in[0];
    const float* rw = (const float*)d_in[1];
    const float* w1 = (const float*)d_in[2];
    const float* b1 = (const float*)d_in[3];
    const float* w2 = (const float*)d_in[4];
    const float* b2 = (const float*)d_in[5];
    float* out = (float*)d_out;

    cudaFuncSetAttribute(moe_mma<1>, cudaFuncAttributeMaxDynamicSharedMemorySize, SMEM_BYTES);
    cudaFuncSetAttribute(moe_mma<2>, cudaFuncAttributeMaxDynamicSharedMemorySize, SMEM_BYTES);

    cudaMemsetAsync(out, 0, (size_t)NTOK * DM * sizeof(float), 0);
    zero_kernel<<<1, 32>>>();
    router_kernel<<<RBLK, 256>>>(x, rw);
    prep_kernel<<<1, 256>>>(out, out_size);
    scatter_pad_kernel<<<NTOK / 256 + NKP_MAX / 256, 256>>>();
    moe_mma<1><<<dim3(FF / 256, MAX_TILES), 256, SMEM_BYTES>>>(x, w1, b1, nullptr);
    moe_mma<2><<<dim3(DM / 256, MAX_TILES), 256, SMEM_BYTES>>>(x, w2, b2, out);
}

// round 11
// speedup vs baseline: 1.3305x; 1.2690x over previous
#include <cuda_runtime.h>
#include <cuda_fp16.h>
#include <math.h>
#include <stdint.h>

// Problem: x:(8,4096,512) f32, router_w:(512,8), w1:(8,512,2048), b1:(8,2048),
//          w2:(8,2048,512), b2:(8,512). Output: out (8*4096*512) f32 + aux_loss.
#define NTOK 32768
#define DM   512
#define FF   2048
#define EE   8
#define NK   (NTOK * 2)
#define MAX_TILES 520
#define NKP_MAX (MAX_TILES * 128)
#define RBLK 512
#define RWARPS (RBLK * 8)

// ---------------- device scratch (static, no allocation) ----------------
__device__ float g_H[(size_t)NKP_MAX * FF];       // expert-hidden scratch
__device__ int   g_topk_idx[NK];
__device__ float g_topk_w[NK];
__device__ int   g_cnt[EE];
__device__ int   g_off[EE];
__device__ int   g_cur[EE];
__device__ int   g_top1[EE];
__device__ int   g_list[NKP_MAX];
__device__ float g_wl[NKP_MAX];
__device__ float g_prob_part[RWARPS * EE];
__device__ int   g_tile_e[MAX_TILES];
__device__ int   g_tile_base[MAX_TILES];
__device__ int   g_tile_valid[MAX_TILES];
__device__ int   g_ntiles;

__device__ __forceinline__ uint32_t pack_h2(float lo, float hi) {
    __half2 h = __floats2half2_rn(lo, hi);    // .x = lo (low half = first k elem)
    return *(uint32_t*)&h;
}
__device__ __forceinline__ void mma_f16(float* d, const uint32_t* a, const uint32_t* b) {
    asm volatile(
        "mma.sync.aligned.m16n8k16.row.col.f32.f16.f16.f32 "
        "{%0,%1,%2,%3}, {%4,%5,%6,%7}, {%8,%9}, {%0,%1,%2,%3};\n"
        : "+f"(d[0]), "+f"(d[1]), "+f"(d[2]), "+f"(d[3])
        : "r"(a[0]), "r"(a[1]), "r"(a[2]), "r"(a[3]), "r"(b[0]), "r"(b[1]));
}
__device__ __forceinline__ void red_add_v2(float* addr, float a, float b) {
    asm volatile("red.global.add.v2.f32 [%0], {%1, %2};"
                 :: "l"(addr), "f"(a), "f"(b) : "memory");
}
__device__ __forceinline__ float gelu_exact(float v) {
    return 0.5f * v * (1.0f + erff(v * 0.70710678118654752f));
}

// ---------------- zero small state ----------------
__global__ void zero_kernel() {
    int t = threadIdx.x;
    if (t < EE) { g_cnt[t] = 0; g_cur[t] = 0; g_top1[t] = 0; }
}

// ---------------- router ----------------
__global__ __launch_bounds__(256) void router_kernel(
        const float* __restrict__ x, const float* __restrict__ rw) {
    __shared__ float s_rw[EE * DM];
    int tid = threadIdx.x;
    for (int i = tid; i < DM * EE; i += 256) {
        int d = i >> 3, e = i & 7;
        s_rw[e * DM + d] = rw[i];
    }
    __syncthreads();
    int warp = tid >> 5, lane = tid & 31;
    float psum[EE];
#pragma unroll
    for (int e = 0; e < EE; e++) psum[e] = 0.f;
    for (int it = 0; it < 8; it++) {
        int t = blockIdx.x * 64 + warp * 8 + it;
        const float* xr = x + (size_t)t * DM;
        float acc[EE];
#pragma unroll
        for (int e = 0; e < EE; e++) acc[e] = 0.f;
#pragma unroll 4
        for (int j = 0; j < 16; j++) {
            float xv = xr[lane + 32 * j];
#pragma unroll
            for (int e = 0; e < EE; e++) acc[e] += xv * s_rw[e * DM + lane + 32 * j];
        }
#pragma unroll
        for (int e = 0; e < EE; e++) {
#pragma unroll
            for (int o = 16; o > 0; o >>= 1)
                acc[e] += __shfl_down_sync(0xffffffffu, acc[e], o);
        }
        if (lane == 0) {
            int e0 = 0; float v0 = acc[0];
#pragma unroll
            for (int e = 1; e < EE; e++) if (acc[e] > v0) { v0 = acc[e]; e0 = e; }
            int e1 = -1; float v1 = -INFINITY;
#pragma unroll
            for (int e = 0; e < EE; e++)
                if (e != e0 && acc[e] > v1) { v1 = acc[e]; e1 = e; }
            float ex = expf(v1 - v0);
            float inv = 1.f / (1.f + ex);
            g_topk_idx[2 * t] = e0;  g_topk_idx[2 * t + 1] = e1;
            g_topk_w[2 * t] = inv;   g_topk_w[2 * t + 1] = ex * inv;
            atomicAdd(&g_cnt[e0], 1);
            atomicAdd(&g_cnt[e1], 1);
            atomicAdd(&g_top1[e0], 1);
            float s = 0.f; float pe[EE];
#pragma unroll
            for (int e = 0; e < EE; e++) { pe[e] = expf(acc[e] - v0); s += pe[e]; }
            float is = 1.f / s;
#pragma unroll
            for (int e = 0; e < EE; e++) psum[e] += pe[e] * is;
        }
    }
    if (lane == 0) {
        int wg = blockIdx.x * 8 + warp;
#pragma unroll
        for (int e = 0; e < EE; e++) g_prob_part[wg * EE + e] = psum[e];
    }
}

// ---------------- prep: aligned CSR offsets, tile table, aux loss ----------------
__global__ void prep_kernel(float* __restrict__ out, int out_size) {
    __shared__ float s_part[256];
    __shared__ float s_e[EE];
    int t = threadIdx.x;
    int e = t & 7, chunk = t >> 3;
    float s = 0.f;
    int w0 = chunk * 128;
    for (int w = w0; w < w0 + 128; w++) s += g_prob_part[w * EE + e];
    s_part[t] = s;
    __syncthreads();
    if (t < EE) {
        float tot = 0.f;
        for (int c = 0; c < 32; c++) tot += s_part[c * 8 + t];
        s_e[t] = tot;
    }
    __syncthreads();
    if (t == 0) {
        int o = 0, nt = 0;
        for (int ee = 0; ee < EE; ee++) {
            g_off[ee] = o;
            int cnt = g_cnt[ee];
            int ntl = (cnt + 127) >> 7;
            for (int i = 0; i < ntl; i++) {
                g_tile_e[nt] = ee;
                g_tile_base[nt] = o + i * 128;
                int v = cnt - i * 128;
                g_tile_valid[nt] = v > 128 ? 128 : v;
                nt++;
            }
            o += ntl * 128;
        }
        g_ntiles = nt;
        float aux = 0.f;
        const float invN = 1.f / (float)NTOK;
        for (int ee = 0; ee < EE; ee++)
            aux += (s_e[ee] * invN) * ((float)g_top1[ee] * invN);
        aux *= 0.01f * (float)EE;
        if (out_size > NTOK * DM) out[(size_t)NTOK * DM] = aux;
    }
}

// ---------------- fused scatter + pad (disjoint slot ranges) ----------------
__global__ void scatter_pad_kernel() {
    int b = blockIdx.x;
    if (b < NTOK / 256) {
        int t = b * 256 + threadIdx.x;
#pragma unroll
        for (int k = 0; k < 2; k++) {
            int e = g_topk_idx[2 * t + k];
            int p = atomicAdd(&g_cur[e], 1);
            int s = g_off[e] + p;
            g_list[s] = t;
            g_wl[s] = g_topk_w[2 * t + k];
        }
    } else {
        int s = (b - NTOK / 256) * 256 + threadIdx.x;
        if (s >= NKP_MAX) return;
        int e = EE - 1;
        for (int i = 1; i < EE; i++) if (s < g_off[i]) { e = i - 1; break; }
        if (s >= g_off[e] + g_cnt[e]) { g_list[s] = 0; g_wl[s] = 0.f; }
    }
}

// ---------------- fp16 warp-MMA grouped GEMM ----------------
// CTA tile 128x256, BK=16, 256 threads = 8 warps (2x4), warp tile 64x64.
// fp16 inputs (rn), fp32 accum via mma.m16n8k16.
// SMEM (packed half2 words):
//   A: [m 0..127][word 0..7]   stride ASTRW=12 words  (word w = k{2w,2w+1})
//   B: [kpair 0..7][n 0..255]  stride BSTRW=264 words (word = {B[2kp][n],B[2kp+1][n]})
// Bank-verified: fragment LDS and STS.128 phases conflict-free.
#define ASTRW 12
#define BSTRW 264
#define A_STW (128 * ASTRW)   // 1536 words / stage
#define B_STW (8 * BSTRW)     // 2112 words / stage

template<int PHASE>
__global__ __launch_bounds__(256, 1) void moe_mma(
        const float* __restrict__ x,
        const float* __restrict__ wmat,
        const float* __restrict__ bias_all,
        float* __restrict__ out) {
    constexpr int KD  = (PHASE == 1) ? DM : FF;   // reduction dim
    constexpr int ND  = (PHASE == 1) ? FF : DM;   // output dim (B row stride)
    constexpr int NIT = KD / 16;

    int tile = blockIdx.y;
    if (tile >= g_ntiles) return;
    int e     = g_tile_e[tile];
    int base  = g_tile_base[tile];
    int valid = g_tile_valid[tile];
    int nb    = blockIdx.x * 256;

    __shared__ uint32_t sA[2][A_STW];
    __shared__ uint32_t sB[2][B_STW];

    int t = threadIdx.x;
    int wid = t >> 5, lane = t & 31;
    int g  = lane >> 2;          // 0..7
    int tg = lane & 3;           // 0..3
    int warp_m = (wid >> 2) * 64;
    int warp_n = (wid & 3) * 64;

    // A loader: row r = t&127, k-offset kq = (t>>7)*8 (8 floats -> 4 words, 1 STS.128)
    int r  = t & 127;
    int kq = (t >> 7) * 8;
    const float* arow;
    if (PHASE == 1) {
        int tok = g_list[base + r];
        arow = x + (size_t)tok * DM;
    } else {
        arow = g_H + (size_t)(base + r) * FF;
    }
    // B loader: n word block n0 = (t&63)*4; kpairs kp = (t>>6) + 4*i, i=0,1
    int bn0 = (t & 63) * 4;
    int kp0 = t >> 6;
    const float* Bsrc = wmat + (size_t)e * KD * ND + nb;  // [k][n], row stride ND

    float acc[4][8][4];
#pragma unroll
    for (int mt = 0; mt < 4; mt++)
#pragma unroll
        for (int nt = 0; nt < 8; nt++)
#pragma unroll
            for (int i = 0; i < 4; i++) acc[mt][nt][i] = 0.f;

    // ---- prolog: fill stage 0 (kb = 0) ----
    {
        float la[8];
        *(float4*)&la[0] = *(const float4*)(arow + kq);
        *(float4*)&la[4] = *(const float4*)(arow + kq + 4);
        *(uint4*)&sA[0][r * ASTRW + (kq >> 1)] = make_uint4(
            pack_h2(la[0], la[1]), pack_h2(la[2], la[3]),
            pack_h2(la[4], la[5]), pack_h2(la[6], la[7]));
#pragma unroll
        for (int i = 0; i < 2; i++) {
            int kp = kp0 + 4 * i;
            const float* bp = Bsrc + (size_t)(2 * kp) * ND + bn0;
            float4 r0 = *(const float4*)(bp);
            float4 r1 = *(const float4*)(bp + ND);
            *(uint4*)&sB[0][kp * BSTRW + bn0] = make_uint4(
                pack_h2(r0.x, r1.x), pack_h2(r0.y, r1.y),
                pack_h2(r0.z, r1.z), pack_h2(r0.w, r1.w));
        }
        __syncthreads();
    }

    for (int it = 0; it < NIT; it++) {
        int s = it & 1;
        bool more = (it + 1 < NIT);
        int kb = (it + 1) * 16;
        // prefetch next chunk
        float la[8];
        float4 br0[2], br1[2];
        if (more) {
            *(float4*)&la[0] = *(const float4*)(arow + kb + kq);
            *(float4*)&la[4] = *(const float4*)(arow + kb + kq + 4);
#pragma unroll
            for (int i = 0; i < 2; i++) {
                int kp = kp0 + 4 * i;
                const float* bp = Bsrc + (size_t)(kb + 2 * kp) * ND + bn0;
                br0[i] = *(const float4*)(bp);
                br1[i] = *(const float4*)(bp + ND);
            }
        }
        // ---- compute one k16 step from stage s ----
        {
            const uint32_t* As = sA[s];
            const uint32_t* Bs = sB[s];
            uint32_t af[4][4], bf[8][2];
#pragma unroll
            for (int mt = 0; mt < 4; mt++) {
                int m0 = warp_m + mt * 16 + g;
                af[mt][0] = As[m0 * ASTRW + tg];
                af[mt][1] = As[(m0 + 8) * ASTRW + tg];
                af[mt][2] = As[m0 * ASTRW + 4 + tg];
                af[mt][3] = As[(m0 + 8) * ASTRW + 4 + tg];
            }
#pragma unroll
            for (int nt = 0; nt < 8; nt++) {
                int n0 = warp_n + nt * 8 + g;
                bf[nt][0] = Bs[tg * BSTRW + n0];
                bf[nt][1] = Bs[(4 + tg) * BSTRW + n0];
            }
#pragma unroll
            for (int mt = 0; mt < 4; mt++)
#pragma unroll
                for (int nt = 0; nt < 8; nt++)
                    mma_f16(acc[mt][nt], af[mt], bf[nt]);
        }
        // store next stage, sync
        if (more) {
            int sn = s ^ 1;
            *(uint4*)&sA[sn][r * ASTRW + (kq >> 1)] = make_uint4(
                pack_h2(la[0], la[1]), pack_h2(la[2], la[3]),
                pack_h2(la[4], la[5]), pack_h2(la[6], la[7]));
#pragma unroll
            for (int i = 0; i < 2; i++) {
                int kp = kp0 + 4 * i;
                *(uint4*)&sB[sn][kp * BSTRW + bn0] = make_uint4(
                    pack_h2(br0[i].x, br1[i].x), pack_h2(br0[i].y, br1[i].y),
                    pack_h2(br0[i].z, br1[i].z), pack_h2(br0[i].w, br1[i].w));
            }
            __syncthreads();
        }
    }

    // ---------------- epilogue ----------------
    // Fragment D mapping: c0:(row=g, col=tg*2) c1:(col+1) c2:(row+8) c3:(row+8,col+1)
    const float* bvec = bias_all + (size_t)e * ND + nb;
    if (PHASE == 1) {
#pragma unroll
        for (int mt = 0; mt < 4; mt++) {
            int rr0 = warp_m + mt * 16 + g;
            float* H0 = g_H + (size_t)(base + rr0) * FF + nb;
            float* H1 = g_H + (size_t)(base + rr0 + 8) * FF + nb;
#pragma unroll
            for (int nt = 0; nt < 8; nt++) {
                int c = warp_n + nt * 8 + tg * 2;
                float b0 = bvec[c], b1 = bvec[c + 1];
                float2 v0, v1;
                v0.x = gelu_exact(acc[mt][nt][0] + b0);
                v0.y = gelu_exact(acc[mt][nt][1] + b1);
                v1.x = gelu_exact(acc[mt][nt][2] + b0);
                v1.y = gelu_exact(acc[mt][nt][3] + b1);
                *(float2*)(H0 + c) = v0;
                *(float2*)(H1 + c) = v1;
            }
        }
    } else {
#pragma unroll
        for (int mt = 0; mt < 4; mt++) {
            int rr0 = warp_m + mt * 16 + g;
#pragma unroll
            for (int half = 0; half < 2; half++) {
                int rr = rr0 + half * 8;
                if (rr < valid) {
                    int slot = base + rr;
                    int tok  = g_list[slot];
                    float gw = g_wl[slot];
                    float* O = out + (size_t)tok * DM + nb;
#pragma unroll
                    for (int nt = 0; nt < 8; nt++) {
                        int c = warp_n + nt * 8 + tg * 2;
                        red_add_v2(O + c,
                                   gw * (acc[mt][nt][half * 2]     + bvec[c]),
                                   gw * (acc[mt][nt][half * 2 + 1] + bvec[c + 1]));
                    }
                }
            }
        }
    }
}

// ---------------- launch ----------------
extern "C" void kernel_launch(void* const* d_in, const int* in_sizes, int n_in,
                              void* d_out, int out_size) {
    const float* x  = (const float*)d_in[0];
    const float* rw = (const float*)d_in[1];
    const float* w1 = (const float*)d_in[2];
    const float* b1 = (const float*)d_in[3];
    const float* w2 = (const float*)d_in[4];
    const float* b2 = (const float*)d_in[5];
    float* out = (float*)d_out;

    cudaMemsetAsync(out, 0, (size_t)NTOK * DM * sizeof(float), 0);
    zero_kernel<<<1, 32>>>();
    router_kernel<<<RBLK, 256>>>(x, rw);
    prep_kernel<<<1, 256>>>(out, out_size);
    scatter_pad_kernel<<<NTOK / 256 + NKP_MAX / 256, 256>>>();
    moe_mma<1><<<dim3(FF / 256, MAX_TILES), 256>>>(x, w1, b1, nullptr);
    moe_mma<2><<<dim3(DM / 256, MAX_TILES), 256>>>(x, w2, b2, out);
}

// round 14
// speedup vs baseline: 1.7214x; 1.2938x over previous
#include <cuda_runtime.h>
#include <cuda_fp16.h>
#include <math.h>
#include <stdint.h>

// Problem: x:(8,4096,512) f32, router_w:(512,8), w1:(8,512,2048), b1:(8,2048),
//          w2:(8,2048,512), b2:(8,512). Output: out (8*4096*512) f32 + aux_loss.
#define NTOK 32768
#define DM   512
#define FF   2048
#define EE   8
#define NK   (NTOK * 2)
#define MAX_TILES 520
#define NKP_MAX (MAX_TILES * 128)
#define RBLK 512
#define RWARPS (RBLK * 8)

// ---------------- device scratch (static, no allocation) ----------------
__device__ __half   g_Hh[(size_t)NKP_MAX * FF];          // fp16 expert-hidden
__device__ __half   g_xh[(size_t)NTOK * DM];             // fp16 x
__device__ uint32_t g_w1i[(size_t)EE * (DM / 2) * FF];   // w1 k-pair-interleaved half2
__device__ uint32_t g_w2i[(size_t)EE * (FF / 2) * DM];   // w2 k-pair-interleaved half2
__device__ int   g_topk_idx[NK];
__device__ float g_topk_w[NK];
__device__ int   g_cnt[EE];
__device__ int   g_off[EE];
__device__ int   g_cur[EE];
__device__ int   g_top1[EE];
__device__ int   g_list[NKP_MAX];
__device__ float g_wl[NKP_MAX];
__device__ float g_prob_part[RWARPS * EE];
__device__ int   g_tile_e[MAX_TILES];
__device__ int   g_tile_base[MAX_TILES];
__device__ int   g_tile_valid[MAX_TILES];
__device__ int   g_ntiles;

__device__ __forceinline__ uint32_t pack_h2(float lo, float hi) {
    __half2 h = __floats2half2_rn(lo, hi);    // .x = lo (low half = first k elem)
    return *(uint32_t*)&h;
}
__device__ __forceinline__ void mma_f16(float* d, const uint32_t* a, const uint32_t* b) {
    asm volatile(
        "mma.sync.aligned.m16n8k16.row.col.f32.f16.f16.f32 "
        "{%0,%1,%2,%3}, {%4,%5,%6,%7}, {%8,%9}, {%0,%1,%2,%3};\n"
        : "+f"(d[0]), "+f"(d[1]), "+f"(d[2]), "+f"(d[3])
        : "r"(a[0]), "r"(a[1]), "r"(a[2]), "r"(a[3]), "r"(b[0]), "r"(b[1]));
}
__device__ __forceinline__ void red_add_v2(float* addr, float a, float b) {
    asm volatile("red.global.add.v2.f32 [%0], {%1, %2};"
                 :: "l"(addr), "f"(a), "f"(b) : "memory");
}
__device__ __forceinline__ float gelu_exact(float v) {
    return 0.5f * v * (1.0f + erff(v * 0.70710678118654752f));
}

// ---------------- zero small state ----------------
__global__ void zero_kernel() {
    int t = threadIdx.x;
    if (t < EE) { g_cnt[t] = 0; g_cur[t] = 0; g_top1[t] = 0; }
}

// ---------------- fp16 pre-conversion ----------------
__global__ __launch_bounds__(256) void conv_x_kernel(const float* __restrict__ x) {
    size_t idx = (size_t)blockIdx.x * 256 + threadIdx.x;   // one 8-float unit
    const float* s = x + idx * 8;
    float4 a = *(const float4*)s;
    float4 b = *(const float4*)(s + 4);
    uint32_t* d = (uint32_t*)g_xh + idx * 4;
    *(uint4*)d = make_uint4(pack_h2(a.x, a.y), pack_h2(a.z, a.w),
                            pack_h2(b.x, b.y), pack_h2(b.z, b.w));
}
// dst[e][kp][n] = half2(src[e][2kp][n], src[e][2kp+1][n]); 4 n per thread.
// NOTE: dst must be bound INSIDE device code — __device__ symbols are not
// valid host-side kernel arguments (that was the R12/R13 all-zeros bug).
template<int KH, int ND>
__device__ __forceinline__ void conv_w_body(const float* __restrict__ src,
                                            uint32_t* __restrict__ dst) {
    int idx = blockIdx.x * 256 + threadIdx.x;
    constexpr int nq = ND >> 2;
    int n4 = (idx % nq) * 4;
    int rest = idx / nq;
    int kp = rest % KH;
    int e  = rest / KH;
    const float* s0 = src + ((size_t)e * KH * 2 + 2 * kp) * ND + n4;
    float4 a = *(const float4*)s0;
    float4 b = *(const float4*)(s0 + ND);
    uint32_t* d = dst + ((size_t)e * KH + kp) * ND + n4;
    *(uint4*)d = make_uint4(pack_h2(a.x, b.x), pack_h2(a.y, b.y),
                            pack_h2(a.z, b.z), pack_h2(a.w, b.w));
}
__global__ __launch_bounds__(256) void conv_w1_kernel(const float* __restrict__ w1) {
    conv_w_body<DM / 2, FF>(w1, g_w1i);
}
__global__ __launch_bounds__(256) void conv_w2_kernel(const float* __restrict__ w2) {
    conv_w_body<FF / 2, DM>(w2, g_w2i);
}

// ---------------- router ----------------
__global__ __launch_bounds__(256) void router_kernel(
        const float* __restrict__ x, const float* __restrict__ rw) {
    __shared__ float s_rw[EE * DM];
    int tid = threadIdx.x;
    for (int i = tid; i < DM * EE; i += 256) {
        int d = i >> 3, e = i & 7;
        s_rw[e * DM + d] = rw[i];
    }
    __syncthreads();
    int warp = tid >> 5, lane = tid & 31;
    float psum[EE];
#pragma unroll
    for (int e = 0; e < EE; e++) psum[e] = 0.f;
    for (int it = 0; it < 8; it++) {
        int t = blockIdx.x * 64 + warp * 8 + it;
        const float* xr = x + (size_t)t * DM;
        float acc[EE];
#pragma unroll
        for (int e = 0; e < EE; e++) acc[e] = 0.f;
#pragma unroll 4
        for (int j = 0; j < 16; j++) {
            float xv = xr[lane + 32 * j];
#pragma unroll
            for (int e = 0; e < EE; e++) acc[e] += xv * s_rw[e * DM + lane + 32 * j];
        }
#pragma unroll
        for (int e = 0; e < EE; e++) {
#pragma unroll
            for (int o = 16; o > 0; o >>= 1)
                acc[e] += __shfl_down_sync(0xffffffffu, acc[e], o);
        }
        if (lane == 0) {
            int e0 = 0; float v0 = acc[0];
#pragma unroll
            for (int e = 1; e < EE; e++) if (acc[e] > v0) { v0 = acc[e]; e0 = e; }
            int e1 = -1; float v1 = -INFINITY;
#pragma unroll
            for (int e = 0; e < EE; e++)
                if (e != e0 && acc[e] > v1) { v1 = acc[e]; e1 = e; }
            float ex = expf(v1 - v0);
            float inv = 1.f / (1.f + ex);
            g_topk_idx[2 * t] = e0;  g_topk_idx[2 * t + 1] = e1;
            g_topk_w[2 * t] = inv;   g_topk_w[2 * t + 1] = ex * inv;
            atomicAdd(&g_cnt[e0], 1);
            atomicAdd(&g_cnt[e1], 1);
            atomicAdd(&g_top1[e0], 1);
            float s = 0.f; float pe[EE];
#pragma unroll
            for (int e = 0; e < EE; e++) { pe[e] = expf(acc[e] - v0); s += pe[e]; }
            float is = 1.f / s;
#pragma unroll
            for (int e = 0; e < EE; e++) psum[e] += pe[e] * is;
        }
    }
    if (lane == 0) {
        int wg = blockIdx.x * 8 + warp;
#pragma unroll
        for (int e = 0; e < EE; e++) g_prob_part[wg * EE + e] = psum[e];
    }
}

// ---------------- prep: aligned CSR offsets, tile table, aux loss ----------------
__global__ void prep_kernel(float* __restrict__ out, int out_size) {
    __shared__ float s_part[256];
    __shared__ float s_e[EE];
    int t = threadIdx.x;
    int e = t & 7, chunk = t >> 3;
    float s = 0.f;
    int w0 = chunk * 128;
    for (int w = w0; w < w0 + 128; w++) s += g_prob_part[w * EE + e];
    s_part[t] = s;
    __syncthreads();
    if (t < EE) {
        float tot = 0.f;
        for (int c = 0; c < 32; c++) tot += s_part[c * 8 + t];
        s_e[t] = tot;
    }
    __syncthreads();
    if (t == 0) {
        int o = 0, nt = 0;
        for (int ee = 0; ee < EE; ee++) {
            g_off[ee] = o;
            int cnt = g_cnt[ee];
            int ntl = (cnt + 127) >> 7;
            for (int i = 0; i < ntl; i++) {
                g_tile_e[nt] = ee;
                g_tile_base[nt] = o + i * 128;
                int v = cnt - i * 128;
                g_tile_valid[nt] = v > 128 ? 128 : v;
                nt++;
            }
            o += ntl * 128;
        }
        g_ntiles = nt;
        float aux = 0.f;
        const float invN = 1.f / (float)NTOK;
        for (int ee = 0; ee < EE; ee++)
            aux += (s_e[ee] * invN) * ((float)g_top1[ee] * invN);
        aux *= 0.01f * (float)EE;
        if (out_size > NTOK * DM) out[(size_t)NTOK * DM] = aux;
    }
}

// ---------------- fused scatter + pad (disjoint slot ranges) ----------------
__global__ void scatter_pad_kernel() {
    int b = blockIdx.x;
    if (b < NTOK / 256) {
        int t = b * 256 + threadIdx.x;
#pragma unroll
        for (int k = 0; k < 2; k++) {
            int e = g_topk_idx[2 * t + k];
            int p = atomicAdd(&g_cur[e], 1);
            int s = g_off[e] + p;
            g_list[s] = t;
            g_wl[s] = g_topk_w[2 * t + k];
        }
    } else {
        int s = (b - NTOK / 256) * 256 + threadIdx.x;
        if (s >= NKP_MAX) return;
        int e = EE - 1;
        for (int i = 1; i < EE; i++) if (s < g_off[i]) { e = i - 1; break; }
        if (s >= g_off[e] + g_cnt[e]) { g_list[s] = 0; g_wl[s] = 0.f; }
    }
}

// ---------------- fp16 warp-MMA grouped GEMM (sync double-buffer) ----------------
// CTA tile 128x256, BK=16, 256 threads = 8 warps (2x4), warp tile 64x64.
// Preconverted half2 sources: mainloop = 3x LDG.128 + 3x STS.128 per thread-iter.
// SMEM (half2 words): A [m][kword] stride 12; B [kpair][n] stride 264.
#define ASTRW 12
#define BSTRW 264
#define A_STW (128 * ASTRW)   // 1536 words / stage
#define B_STW (8 * BSTRW)     // 2112 words / stage

template<int PHASE>
__global__ __launch_bounds__(256, 1) void moe_mma(
        const float* __restrict__ bias_all,
        float* __restrict__ out) {
    constexpr int KD  = (PHASE == 1) ? DM : FF;   // reduction dim
    constexpr int ND  = (PHASE == 1) ? FF : DM;   // output dim
    constexpr int NIT = KD / 16;

    int tile = blockIdx.y;
    if (tile >= g_ntiles) return;
    int e     = g_tile_e[tile];
    int base  = g_tile_base[tile];
    int valid = g_tile_valid[tile];
    int nb    = blockIdx.x * 256;

    __shared__ uint32_t sA[2][A_STW];
    __shared__ uint32_t sB[2][B_STW];

    int t = threadIdx.x;
    int wid = t >> 5, lane = t & 31;
    int g  = lane >> 2;          // 0..7
    int tg = lane & 3;           // 0..3
    int warp_m = (wid >> 2) * 64;
    int warp_n = (wid & 3) * 64;

    // A loader: row r = t&127, word offset aoff = (t>>7)*4 (one uint4 per iter)
    int r    = t & 127;
    int aoff = (t >> 7) * 4;
    const uint32_t* arowW;
    if (PHASE == 1) {
        int tok = g_list[base + r];
        arowW = (const uint32_t*)(g_xh + (size_t)tok * DM);
    } else {
        arowW = (const uint32_t*)(g_Hh + (size_t)(base + r) * FF);
    }
    // B loader: n word block bn0 = (t&63)*4; kpairs kp0 and kp0+4
    int bn0 = (t & 63) * 4;
    int kp0 = t >> 6;
    const uint32_t* Bi = ((PHASE == 1) ? g_w1i : g_w2i)
                         + (size_t)e * (KD / 2) * ND + nb;  // word units

    float acc[4][8][4];
#pragma unroll
    for (int mt = 0; mt < 4; mt++)
#pragma unroll
        for (int nt = 0; nt < 8; nt++)
#pragma unroll
            for (int i = 0; i < 4; i++) acc[mt][nt][i] = 0.f;

    // ---- prolog: fill stage 0 (chunk 0) ----
    {
        uint4 av = *(const uint4*)(arowW + aoff);
        uint4 b0 = *(const uint4*)(Bi + (size_t)kp0 * ND + bn0);
        uint4 b1 = *(const uint4*)(Bi + (size_t)(kp0 + 4) * ND + bn0);
        *(uint4*)&sA[0][r * ASTRW + aoff] = av;
        *(uint4*)&sB[0][kp0 * BSTRW + bn0] = b0;
        *(uint4*)&sB[0][(kp0 + 4) * BSTRW + bn0] = b1;
        __syncthreads();
    }

    for (int it = 0; it < NIT; it++) {
        int s = it & 1;
        bool more = (it + 1 < NIT);
        uint4 av, b0, b1;
        if (more) {
            int kwp = (it + 1) * 8;                 // word offset / kpair base of next chunk
            av = *(const uint4*)(arowW + kwp + aoff);
            b0 = *(const uint4*)(Bi + (size_t)(kwp + kp0) * ND + bn0);
            b1 = *(const uint4*)(Bi + (size_t)(kwp + kp0 + 4) * ND + bn0);
        }
        // ---- compute one k16 step from stage s ----
        {
            const uint32_t* As = sA[s];
            const uint32_t* Bs = sB[s];
            uint32_t af[4][4], bf[8][2];
#pragma unroll
            for (int mt = 0; mt < 4; mt++) {
                int m0 = warp_m + mt * 16 + g;
                af[mt][0] = As[m0 * ASTRW + tg];
                af[mt][1] = As[(m0 + 8) * ASTRW + tg];
                af[mt][2] = As[m0 * ASTRW + 4 + tg];
                af[mt][3] = As[(m0 + 8) * ASTRW + 4 + tg];
            }
#pragma unroll
            for (int nt = 0; nt < 8; nt++) {
                int n0 = warp_n + nt * 8 + g;
                bf[nt][0] = Bs[tg * BSTRW + n0];
                bf[nt][1] = Bs[(4 + tg) * BSTRW + n0];
            }
#pragma unroll
            for (int mt = 0; mt < 4; mt++)
#pragma unroll
                for (int nt = 0; nt < 8; nt++)
                    mma_f16(acc[mt][nt], af[mt], bf[nt]);
        }
        if (more) {
            int sn = s ^ 1;
            *(uint4*)&sA[sn][r * ASTRW + aoff] = av;
            *(uint4*)&sB[sn][kp0 * BSTRW + bn0] = b0;
            *(uint4*)&sB[sn][(kp0 + 4) * BSTRW + bn0] = b1;
            __syncthreads();
        }
    }

    // ---------------- epilogue ----------------
    // Fragment D mapping: c0:(row=g, col=tg*2) c1:(col+1) c2:(row+8) c3:(row+8,col+1)
    const float* bvec = bias_all + (size_t)e * ND + nb;
    if (PHASE == 1) {
#pragma unroll
        for (int mt = 0; mt < 4; mt++) {
            int rr0 = warp_m + mt * 16 + g;
            __half* H0 = g_Hh + (size_t)(base + rr0) * FF + nb;
            __half* H1 = g_Hh + (size_t)(base + rr0 + 8) * FF + nb;
#pragma unroll
            for (int nt = 0; nt < 8; nt++) {
                int c = warp_n + nt * 8 + tg * 2;
                float b0 = bvec[c], b1 = bvec[c + 1];
                *(uint32_t*)(H0 + c) = pack_h2(gelu_exact(acc[mt][nt][0] + b0),
                                               gelu_exact(acc[mt][nt][1] + b1));
                *(uint32_t*)(H1 + c) = pack_h2(gelu_exact(acc[mt][nt][2] + b0),
                                               gelu_exact(acc[mt][nt][3] + b1));
            }
        }
    } else {
#pragma unroll
        for (int mt = 0; mt < 4; mt++) {
            int rr0 = warp_m + mt * 16 + g;
#pragma unroll
            for (int half = 0; half < 2; half++) {
                int rr = rr0 + half * 8;
                if (rr < valid) {
                    int slot = base + rr;
                    int tok  = g_list[slot];
                    float gw = g_wl[slot];
                    float* O = out + (size_t)tok * DM + nb;
#pragma unroll
                    for (int nt = 0; nt < 8; nt++) {
                        int c = warp_n + nt * 8 + tg * 2;
                        red_add_v2(O + c,
                                   gw * (acc[mt][nt][half * 2]     + bvec[c]),
                                   gw * (acc[mt][nt][half * 2 + 1] + bvec[c + 1]));
                    }
                }
            }
        }
    }
}

// ---------------- launch ----------------
extern "C" void kernel_launch(void* const* d_in, const int* in_sizes, int n_in,
                              void* d_out, int out_size) {
    const float* x  = (const float*)d_in[0];
    const float* rw = (const float*)d_in[1];
    const float* w1 = (const float*)d_in[2];
    const float* b1 = (const float*)d_in[3];
    const float* w2 = (const float*)d_in[4];
    const float* b2 = (const float*)d_in[5];
    float* out = (float*)d_out;

    cudaMemsetAsync(out, 0, (size_t)NTOK * DM * sizeof(float), 0);
    zero_kernel<<<1, 32>>>();
    conv_x_kernel<<<(NTOK * DM / 8) / 256, 256>>>(x);
    conv_w1_kernel<<<(EE * (DM / 2) * FF / 4) / 256, 256>>>(w1);
    conv_w2_kernel<<<(EE * (FF / 2) * DM / 4) / 256, 256>>>(w2);
    router_kernel<<<RBLK, 256>>>(x, rw);
    prep_kernel<<<1, 256>>>(out, out_size);
    scatter_pad_kernel<<<NTOK / 256 + NKP_MAX / 256, 256>>>();
    moe_mma<1><<<dim3(FF / 256, MAX_TILES), 256>>>(b1, out);
    moe_mma<2><<<dim3(DM / 256, MAX_TILES), 256>>>(b2, out);
}

// round 16
// speedup vs baseline: 1.8437x; 1.0711x over previous
#include <cuda_runtime.h>
#include <cuda_fp16.h>
#include <math.h>
#include <stdint.h>

// Problem: x:(8,4096,512) f32, router_w:(512,8), w1:(8,512,2048), b1:(8,2048),
//          w2:(8,2048,512), b2:(8,512). Output: out (8*4096*512) f32 + aux_loss.
#define NTOK 32768
#define DM   512
#define FF   2048
#define EE   8
#define NK   (NTOK * 2)
#define MAX_TILES 520
#define NKP_MAX (MAX_TILES * 128)
#define RBLK 512
#define RWARPS (RBLK * 8)

// ---------------- device scratch (static, no allocation) ----------------
__device__ __half   g_Hh[(size_t)NKP_MAX * FF];          // fp16 expert-hidden
__device__ __half   g_xh[(size_t)NTOK * DM];             // fp16 x
__device__ uint32_t g_w1i[(size_t)EE * (DM / 2) * FF];   // w1 k-pair-interleaved half2
__device__ uint32_t g_w2i[(size_t)EE * (FF / 2) * DM];   // w2 k-pair-interleaved half2
__device__ int   g_topk_idx[NK];
__device__ float g_topk_w[NK];
__device__ int   g_cnt[EE];
__device__ int   g_off[EE];
__device__ int   g_cur[EE];
__device__ int   g_top1[EE];
__device__ int   g_list[NKP_MAX];
__device__ float g_wl[NKP_MAX];
__device__ float g_prob_part[RWARPS * EE];
__device__ int   g_tile_e[MAX_TILES];
__device__ int   g_tile_base[MAX_TILES];
__device__ int   g_tile_valid[MAX_TILES];
__device__ int   g_ntiles;

__device__ __forceinline__ uint32_t pack_h2(float lo, float hi) {
    __half2 h = __floats2half2_rn(lo, hi);    // .x = lo (low half = first k elem)
    return *(uint32_t*)&h;
}
__device__ __forceinline__ void mma_f16(float* d, const uint32_t* a, const uint32_t* b) {
    asm volatile(
        "mma.sync.aligned.m16n8k16.row.col.f32.f16.f16.f32 "
        "{%0,%1,%2,%3}, {%4,%5,%6,%7}, {%8,%9}, {%0,%1,%2,%3};\n"
        : "+f"(d[0]), "+f"(d[1]), "+f"(d[2]), "+f"(d[3])
        : "r"(a[0]), "r"(a[1]), "r"(a[2]), "r"(a[3]), "r"(b[0]), "r"(b[1]));
}
__device__ __forceinline__ void red_add_v2(float* addr, float a, float b) {
    asm volatile("red.global.add.v2.f32 [%0], {%1, %2};"
                 :: "l"(addr), "f"(a), "f"(b) : "memory");
}
__device__ __forceinline__ void cp16(uint32_t saddr, const void* gptr) {
    asm volatile("cp.async.cg.shared.global [%0], [%1], 16;"
                 :: "r"(saddr), "l"(gptr) : "memory");
}
#define CP_COMMIT() asm volatile("cp.async.commit_group;" ::: "memory")
#define CP_WAIT1()  asm volatile("cp.async.wait_group 1;" ::: "memory")
#define CP_WAIT0()  asm volatile("cp.async.wait_group 0;" ::: "memory")

__device__ __forceinline__ float gelu_exact(float v) {
    return 0.5f * v * (1.0f + erff(v * 0.70710678118654752f));
}

// ---------------- zero small state ----------------
__global__ void zero_kernel() {
    int t = threadIdx.x;
    if (t < EE) { g_cnt[t] = 0; g_cur[t] = 0; g_top1[t] = 0; }
}

// ---------------- fp16 pre-conversion ----------------
__global__ __launch_bounds__(256) void conv_x_kernel(const float* __restrict__ x) {
    size_t idx = (size_t)blockIdx.x * 256 + threadIdx.x;   // one 8-float unit
    const float* s = x + idx * 8;
    float4 a = *(const float4*)s;
    float4 b = *(const float4*)(s + 4);
    uint32_t* d = (uint32_t*)g_xh + idx * 4;
    *(uint4*)d = make_uint4(pack_h2(a.x, a.y), pack_h2(a.z, a.w),
                            pack_h2(b.x, b.y), pack_h2(b.z, b.w));
}
// dst[e][kp][n] = half2(src[e][2kp][n], src[e][2kp+1][n]); 4 n per thread.
// NOTE: dst must be bound INSIDE device code — __device__ symbols are not
// valid host-side kernel arguments (that was the R12/R13 all-zeros bug).
template<int KH, int ND>
__device__ __forceinline__ void conv_w_body(const float* __restrict__ src,
                                            uint32_t* __restrict__ dst) {
    int idx = blockIdx.x * 256 + threadIdx.x;
    constexpr int nq = ND >> 2;
    int n4 = (idx % nq) * 4;
    int rest = idx / nq;
    int kp = rest % KH;
    int e  = rest / KH;
    const float* s0 = src + ((size_t)e * KH * 2 + 2 * kp) * ND + n4;
    float4 a = *(const float4*)s0;
    float4 b = *(const float4*)(s0 + ND);
    uint32_t* d = dst + ((size_t)e * KH + kp) * ND + n4;
    *(uint4*)d = make_uint4(pack_h2(a.x, b.x), pack_h2(a.y, b.y),
                            pack_h2(a.z, b.z), pack_h2(a.w, b.w));
}
__global__ __launch_bounds__(256) void conv_w1_kernel(const float* __restrict__ w1) {
    conv_w_body<DM / 2, FF>(w1, g_w1i);
}
__global__ __launch_bounds__(256) void conv_w2_kernel(const float* __restrict__ w2) {
    conv_w_body<FF / 2, DM>(w2, g_w2i);
}

// ---------------- router ----------------
__global__ __launch_bounds__(256) void router_kernel(
        const float* __restrict__ x, const float* __restrict__ rw) {
    __shared__ float s_rw[EE * DM];
    int tid = threadIdx.x;
    for (int i = tid; i < DM * EE; i += 256) {
        int d = i >> 3, e = i & 7;
        s_rw[e * DM + d] = rw[i];
    }
    __syncthreads();
    int warp = tid >> 5, lane = tid & 31;
    float psum[EE];
#pragma unroll
    for (int e = 0; e < EE; e++) psum[e] = 0.f;
    for (int it = 0; it < 8; it++) {
        int t = blockIdx.x * 64 + warp * 8 + it;
        const float* xr = x + (size_t)t * DM;
        float acc[EE];
#pragma unroll
        for (int e = 0; e < EE; e++) acc[e] = 0.f;
#pragma unroll 4
        for (int j = 0; j < 16; j++) {
            float xv = xr[lane + 32 * j];
#pragma unroll
            for (int e = 0; e < EE; e++) acc[e] += xv * s_rw[e * DM + lane + 32 * j];
        }
#pragma unroll
        for (int e = 0; e < EE; e++) {
#pragma unroll
            for (int o = 16; o > 0; o >>= 1)
                acc[e] += __shfl_down_sync(0xffffffffu, acc[e], o);
        }
        if (lane == 0) {
            int e0 = 0; float v0 = acc[0];
#pragma unroll
            for (int e = 1; e < EE; e++) if (acc[e] > v0) { v0 = acc[e]; e0 = e; }
            int e1 = -1; float v1 = -INFINITY;
#pragma unroll
            for (int e = 0; e < EE; e++)
                if (e != e0 && acc[e] > v1) { v1 = acc[e]; e1 = e; }
            float ex = expf(v1 - v0);
            float inv = 1.f / (1.f + ex);
            g_topk_idx[2 * t] = e0;  g_topk_idx[2 * t + 1] = e1;
            g_topk_w[2 * t] = inv;   g_topk_w[2 * t + 1] = ex * inv;
            atomicAdd(&g_cnt[e0], 1);
            atomicAdd(&g_cnt[e1], 1);
            atomicAdd(&g_top1[e0], 1);
            float s = 0.f; float pe[EE];
#pragma unroll
            for (int e = 0; e < EE; e++) { pe[e] = expf(acc[e] - v0); s += pe[e]; }
            float is = 1.f / s;
#pragma unroll
            for (int e = 0; e < EE; e++) psum[e] += pe[e] * is;
        }
    }
    if (lane == 0) {
        int wg = blockIdx.x * 8 + warp;
#pragma unroll
        for (int e = 0; e < EE; e++) g_prob_part[wg * EE + e] = psum[e];
    }
}

// ---------------- prep: aligned CSR offsets, tile table, aux loss ----------------
__global__ void prep_kernel(float* __restrict__ out, int out_size) {
    __shared__ float s_part[256];
    __shared__ float s_e[EE];
    int t = threadIdx.x;
    int e = t & 7, chunk = t >> 3;
    float s = 0.f;
    int w0 = chunk * 128;
    for (int w = w0; w < w0 + 128; w++) s += g_prob_part[w * EE + e];
    s_part[t] = s;
    __syncthreads();
    if (t < EE) {
        float tot = 0.f;
        for (int c = 0; c < 32; c++) tot += s_part[c * 8 + t];
        s_e[t] = tot;
    }
    __syncthreads();
    if (t == 0) {
        int o = 0, nt = 0;
        for (int ee = 0; ee < EE; ee++) {
            g_off[ee] = o;
            int cnt = g_cnt[ee];
            int ntl = (cnt + 127) >> 7;
            for (int i = 0; i < ntl; i++) {
                g_tile_e[nt] = ee;
                g_tile_base[nt] = o + i * 128;
                int v = cnt - i * 128;
                g_tile_valid[nt] = v > 128 ? 128 : v;
                nt++;
            }
            o += ntl * 128;
        }
        g_ntiles = nt;
        float aux = 0.f;
        const float invN = 1.f / (float)NTOK;
        for (int ee = 0; ee < EE; ee++)
            aux += (s_e[ee] * invN) * ((float)g_top1[ee] * invN);
        aux *= 0.01f * (float)EE;
        if (out_size > NTOK * DM) out[(size_t)NTOK * DM] = aux;
    }
}

// ---------------- fused scatter + pad (disjoint slot ranges) ----------------
__global__ void scatter_pad_kernel() {
    int b = blockIdx.x;
    if (b < NTOK / 256) {
        int t = b * 256 + threadIdx.x;
#pragma unroll
        for (int k = 0; k < 2; k++) {
            int e = g_topk_idx[2 * t + k];
            int p = atomicAdd(&g_cur[e], 1);
            int s = g_off[e] + p;
            g_list[s] = t;
            g_wl[s] = g_topk_w[2 * t + k];
        }
    } else {
        int s = (b - NTOK / 256) * 256 + threadIdx.x;
        if (s >= NKP_MAX) return;
        int e = EE - 1;
        for (int i = 1; i < EE; i++) if (s < g_off[i]) { e = i - 1; break; }
        if (s >= g_off[e] + g_cnt[e]) { g_list[s] = 0; g_wl[s] = 0.f; }
    }
}

// ---------------- fp16 warp-MMA grouped GEMM (cp.async 3-stage) ----------------
// CTA tile 128x256, BK=16, 256 threads = 8 warps (2x4), warp tile 64x64.
// Preconverted half2 sources; loads land in SMEM via cp.async (no staging/STS).
// SMEM (half2 words): A [m][kword] stride 12; B [kpair][n] stride 264.
#define ASTRW 12
#define BSTRW 264
#define A_STW (128 * ASTRW)   // 1536 words / stage
#define B_STW (8 * BSTRW)     // 2112 words / stage

template<int PHASE>
__global__ __launch_bounds__(256, 1) void moe_mma(
        const float* __restrict__ bias_all,
        float* __restrict__ out) {
    constexpr int KD  = (PHASE == 1) ? DM : FF;   // reduction dim
    constexpr int ND  = (PHASE == 1) ? FF : DM;   // output dim
    constexpr int NIT = KD / 16;

    int tile = blockIdx.y;
    if (tile >= g_ntiles) return;
    int e     = g_tile_e[tile];
    int base  = g_tile_base[tile];
    int valid = g_tile_valid[tile];
    int nb    = blockIdx.x * 256;

    __shared__ uint32_t sA[3][A_STW];
    __shared__ uint32_t sB[3][B_STW];

    int t = threadIdx.x;
    int wid = t >> 5, lane = t & 31;
    int g  = lane >> 2;          // 0..7
    int tg = lane & 3;           // 0..3
    int warp_m = (wid >> 2) * 64;
    int warp_n = (wid & 3) * 64;

    // A loader: row r = t&127, word offset aoff = (t>>7)*4 (one 16B unit/iter)
    int r    = t & 127;
    int aoff = (t >> 7) * 4;
    const uint32_t* arowW;
    if (PHASE == 1) {
        int tok = g_list[base + r];
        arowW = (const uint32_t*)(g_xh + (size_t)tok * DM);
    } else {
        arowW = (const uint32_t*)(g_Hh + (size_t)(base + r) * FF);
    }
    // B loader: n word block bn0 = (t&63)*4; kpairs kp0 and kp0+4
    int bn0 = (t & 63) * 4;
    int kp0 = t >> 6;
    const uint32_t* Bi = ((PHASE == 1) ? g_w1i : g_w2i)
                         + (size_t)e * (KD / 2) * ND + nb;  // word units

    uint32_t aw[3], bw0[3], bw1[3];
#pragma unroll
    for (int st = 0; st < 3; st++) {
        aw[st]  = (uint32_t)__cvta_generic_to_shared(&sA[st][r * ASTRW + aoff]);
        bw0[st] = (uint32_t)__cvta_generic_to_shared(&sB[st][kp0 * BSTRW + bn0]);
        bw1[st] = (uint32_t)__cvta_generic_to_shared(&sB[st][(kp0 + 4) * BSTRW + bn0]);
    }

    float acc[4][8][4];
#pragma unroll
    for (int mt = 0; mt < 4; mt++)
#pragma unroll
        for (int nt = 0; nt < 8; nt++)
#pragma unroll
            for (int i = 0; i < 4; i++) acc[mt][nt][i] = 0.f;

    // prologue: issue chunks 0 and 1
#pragma unroll
    for (int c = 0; c < 2; c++) {
        int kwp = c * 8;   // word offset / kpair base of chunk c
        cp16(aw[c], arowW + kwp + aoff);
        cp16(bw0[c], Bi + (size_t)(kwp + kp0) * ND + bn0);
        cp16(bw1[c], Bi + (size_t)(kwp + kp0 + 4) * ND + bn0);
        CP_COMMIT();
    }

    int s = 0;
    for (int it = 0; it < NIT; it++) {
        if (it + 1 < NIT) CP_WAIT1(); else CP_WAIT0();
        __syncthreads();
        // compute one k16 step from stage s
        {
            const uint32_t* As = sA[s];
            const uint32_t* Bs = sB[s];
            uint32_t af[4][4], bf[8][2];
#pragma unroll
            for (int mt = 0; mt < 4; mt++) {
                int m0 = warp_m + mt * 16 + g;
                af[mt][0] = As[m0 * ASTRW + tg];
                af[mt][1] = As[(m0 + 8) * ASTRW + tg];
                af[mt][2] = As[m0 * ASTRW + 4 + tg];
                af[mt][3] = As[(m0 + 8) * ASTRW + 4 + tg];
            }
#pragma unroll
            for (int nt = 0; nt < 8; nt++) {
                int n0 = warp_n + nt * 8 + g;
                bf[nt][0] = Bs[tg * BSTRW + n0];
                bf[nt][1] = Bs[(4 + tg) * BSTRW + n0];
            }
#pragma unroll
            for (int mt = 0; mt < 4; mt++)
#pragma unroll
                for (int nt = 0; nt < 8; nt++)
                    mma_f16(acc[mt][nt], af[mt], bf[nt]);
        }
        // issue chunk it+2 into stage (s+2)%3; that stage's old chunk (it-1)
        // finished compute at iter it-1, fenced by this iter's __syncthreads.
        int nx = it + 2;
        if (nx < NIT) {
            int sn = s + 2; if (sn >= 3) sn -= 3;
            int kwp = nx * 8;
            cp16(aw[sn], arowW + kwp + aoff);
            cp16(bw0[sn], Bi + (size_t)(kwp + kp0) * ND + bn0);
            cp16(bw1[sn], Bi + (size_t)(kwp + kp0 + 4) * ND + bn0);
            CP_COMMIT();
        }
        if (++s == 3) s = 0;
    }

    // ---------------- epilogue ----------------
    // Fragment D mapping: c0:(row=g, col=tg*2) c1:(col+1) c2:(row+8) c3:(row+8,col+1)
    const float* bvec = bias_all + (size_t)e * ND + nb;
    if (PHASE == 1) {
#pragma unroll
        for (int mt = 0; mt < 4; mt++) {
            int rr0 = warp_m + mt * 16 + g;
            __half* H0 = g_Hh + (size_t)(base + rr0) * FF + nb;
            __half* H1 = g_Hh + (size_t)(base + rr0 + 8) * FF + nb;
#pragma unroll
            for (int nt = 0; nt < 8; nt++) {
                int c = warp_n + nt * 8 + tg * 2;
                float b0 = bvec[c], b1 = bvec[c + 1];
                *(uint32_t*)(H0 + c) = pack_h2(gelu_exact(acc[mt][nt][0] + b0),
                                               gelu_exact(acc[mt][nt][1] + b1));
                *(uint32_t*)(H1 + c) = pack_h2(gelu_exact(acc[mt][nt][2] + b0),
                                               gelu_exact(acc[mt][nt][3] + b1));
            }
        }
    } else {
#pragma unroll
        for (int mt = 0; mt < 4; mt++) {
            int rr0 = warp_m + mt * 16 + g;
#pragma unroll
            for (int half = 0; half < 2; half++) {
                int rr = rr0 + half * 8;
                if (rr < valid) {
                    int slot = base + rr;
                    int tok  = g_list[slot];
                    float gw = g_wl[slot];
                    float* O = out + (size_t)tok * DM + nb;
#pragma unroll
                    for (int nt = 0; nt < 8; nt++) {
                        int c = warp_n + nt * 8 + tg * 2;
                        red_add_v2(O + c,
                                   gw * (acc[mt][nt][half * 2]     + bvec[c]),
                                   gw * (acc[mt][nt][half * 2 + 1] + bvec[c + 1]));
                    }
                }
            }
        }
    }
}

// ---------------- launch ----------------
extern "C" void kernel_launch(void* const* d_in, const int* in_sizes, int n_in,
                              void* d_out, int out_size) {
    const float* x  = (const float*)d_in[0];
    const float* rw = (const float*)d_in[1];
    const float* w1 = (const float*)d_in[2];
    const float* b1 = (const float*)d_in[3];
    const float* w2 = (const float*)d_in[4];
    const float* b2 = (const float*)d_in[5];
    float* out = (float*)d_out;

    cudaMemsetAsync(out, 0, (size_t)NTOK * DM * sizeof(float), 0);
    zero_kernel<<<1, 32>>>();
    conv_x_kernel<<<(NTOK * DM / 8) / 256, 256>>>(x);
    conv_w1_kernel<<<(EE * (DM / 2) * FF / 4) / 256, 256>>>(w1);
    conv_w2_kernel<<<(EE * (FF / 2) * DM / 4) / 256, 256>>>(w2);
    router_kernel<<<RBLK, 256>>>(x, rw);
    prep_kernel<<<1, 256>>>(out, out_size);
    scatter_pad_kernel<<<NTOK / 256 + NKP_MAX / 256, 256>>>();
    moe_mma<1><<<dim3(FF / 256, MAX_TILES), 256>>>(b1, out);
    moe_mma<2><<<dim3(DM / 256, MAX_TILES), 256>>>(b2, out);
}

// round 17
// speedup vs baseline: 1.8523x; 1.0047x over previous
#include <cuda_runtime.h>
#include <cuda_fp16.h>
#include <math.h>
#include <stdint.h>

// Problem: x:(8,4096,512) f32, router_w:(512,8), w1:(8,512,2048), b1:(8,2048),
//          w2:(8,2048,512), b2:(8,512). Output: out (8*4096*512) f32 + aux_loss.
#define NTOK 32768
#define DM   512
#define FF   2048
#define EE   8
#define NK   (NTOK * 2)
#define MAX_TILES 520
#define NKP_MAX (MAX_TILES * 128)
#define RBLK 512
#define RWARPS (RBLK * 8)
#define W1BLK ((EE * (DM / 2) * FF / 4) / 256)   // 4096
#define W2BLK ((EE * (FF / 2) * DM / 4) / 256)   // 4096

// ---------------- device scratch (static, no allocation) ----------------
__device__ __half   g_Hh[(size_t)NKP_MAX * FF];          // fp16 expert-hidden
__device__ __half   g_xh[(size_t)NTOK * DM];             // fp16 x
__device__ uint32_t g_w1i[(size_t)EE * (DM / 2) * FF];   // w1 k-pair-interleaved half2
__device__ uint32_t g_w2i[(size_t)EE * (FF / 2) * DM];   // w2 k-pair-interleaved half2
__device__ int   g_topk_idx[NK];
__device__ float g_topk_w[NK];
__device__ int   g_cnt[EE];
__device__ int   g_off[EE];
__device__ int   g_cur[EE];
__device__ int   g_top1[EE];
__device__ int   g_list[NKP_MAX];
__device__ float g_wl[NKP_MAX];
__device__ float g_prob_part[RWARPS * EE];
__device__ int   g_tile_e[MAX_TILES];
__device__ int   g_tile_base[MAX_TILES];
__device__ int   g_tile_valid[MAX_TILES];
__device__ int   g_ntiles;

__device__ __forceinline__ uint32_t pack_h2(float lo, float hi) {
    __half2 h = __floats2half2_rn(lo, hi);    // .x = lo (low half = first k elem)
    return *(uint32_t*)&h;
}
__device__ __forceinline__ void mma_f16(float* d, const uint32_t* a, const uint32_t* b) {
    asm volatile(
        "mma.sync.aligned.m16n8k16.row.col.f32.f16.f16.f32 "
        "{%0,%1,%2,%3}, {%4,%5,%6,%7}, {%8,%9}, {%0,%1,%2,%3};\n"
        : "+f"(d[0]), "+f"(d[1]), "+f"(d[2]), "+f"(d[3])
        : "r"(a[0]), "r"(a[1]), "r"(a[2]), "r"(a[3]), "r"(b[0]), "r"(b[1]));
}
__device__ __forceinline__ void red_add_v2(float* addr, float a, float b) {
    asm volatile("red.global.add.v2.f32 [%0], {%1, %2};"
                 :: "l"(addr), "f"(a), "f"(b) : "memory");
}
__device__ __forceinline__ void cp16(uint32_t saddr, const void* gptr) {
    asm volatile("cp.async.cg.shared.global [%0], [%1], 16;"
                 :: "r"(saddr), "l"(gptr) : "memory");
}
#define CP_COMMIT() asm volatile("cp.async.commit_group;" ::: "memory")
#define CP_WAIT1()  asm volatile("cp.async.wait_group 1;" ::: "memory")
#define CP_WAIT0()  asm volatile("cp.async.wait_group 0;" ::: "memory")

__device__ __forceinline__ float gelu_exact(float v) {
    return 0.5f * v * (1.0f + erff(v * 0.70710678118654752f));
}

// ---------------- fused weight conversion + small-state zero ----------------
// dst[e][kp][n] = half2(src[e][2kp][n], src[e][2kp+1][n]); 4 n per thread.
// NOTE: dst bound INSIDE device code — __device__ symbols are not valid
// host-side kernel args (the R12/R13 all-zeros bug).
template<int KH, int ND>
__device__ __forceinline__ void conv_w_body(int idx, const float* __restrict__ src,
                                            uint32_t* __restrict__ dst) {
    constexpr int nq = ND >> 2;
    int n4 = (idx % nq) * 4;
    int rest = idx / nq;
    int kp = rest % KH;
    int e  = rest / KH;
    const float* s0 = src + ((size_t)e * KH * 2 + 2 * kp) * ND + n4;
    float4 a = *(const float4*)s0;
    float4 b = *(const float4*)(s0 + ND);
    uint32_t* d = dst + ((size_t)e * KH + kp) * ND + n4;
    *(uint4*)d = make_uint4(pack_h2(a.x, b.x), pack_h2(a.y, b.y),
                            pack_h2(a.z, b.z), pack_h2(a.w, b.w));
}
__global__ __launch_bounds__(256) void conv_w_all(const float* __restrict__ w1,
                                                  const float* __restrict__ w2) {
    int b = blockIdx.x, t = threadIdx.x;
    if (b == 0 && t < EE) { g_cnt[t] = 0; g_cur[t] = 0; g_top1[t] = 0; }
    if (b < W1BLK) conv_w_body<DM / 2, FF>(b * 256 + t, w1, g_w1i);
    else           conv_w_body<FF / 2, DM>((b - W1BLK) * 256 + t, w2, g_w2i);
}

// ---------------- router (also emits fp16 x image) ----------------
__global__ __launch_bounds__(256) void router_kernel(
        const float* __restrict__ x, const float* __restrict__ rw) {
    __shared__ float s_rw[EE * DM];
    int tid = threadIdx.x;
    for (int i = tid; i < DM * EE; i += 256) {
        int d = i >> 3, e = i & 7;
        s_rw[e * DM + d] = rw[i];
    }
    __syncthreads();
    int warp = tid >> 5, lane = tid & 31;
    float psum[EE];
#pragma unroll
    for (int e = 0; e < EE; e++) psum[e] = 0.f;
    for (int it = 0; it < 8; it++) {
        int t = blockIdx.x * 64 + warp * 8 + it;
        const float2* xr2 = (const float2*)(x + (size_t)t * DM);
        uint32_t* xw = (uint32_t*)g_xh + (size_t)t * (DM / 2);
        float acc[EE];
#pragma unroll
        for (int e = 0; e < EE; e++) acc[e] = 0.f;
#pragma unroll
        for (int j = 0; j < 8; j++) {
            int idx = lane + 32 * j;          // float2 index (= half2 word index)
            float2 v = xr2[idx];
            xw[idx] = pack_h2(v.x, v.y);      // fp16 x image, coalesced
#pragma unroll
            for (int e = 0; e < EE; e++) {
                float2 w = ((const float2*)(s_rw + e * DM))[idx];
                acc[e] += v.x * w.x + v.y * w.y;
            }
        }
#pragma unroll
        for (int e = 0; e < EE; e++) {
#pragma unroll
            for (int o = 16; o > 0; o >>= 1)
                acc[e] += __shfl_down_sync(0xffffffffu, acc[e], o);
        }
        if (lane == 0) {
            int e0 = 0; float v0 = acc[0];
#pragma unroll
            for (int e = 1; e < EE; e++) if (acc[e] > v0) { v0 = acc[e]; e0 = e; }
            int e1 = -1; float v1 = -INFINITY;
#pragma unroll
            for (int e = 0; e < EE; e++)
                if (e != e0 && acc[e] > v1) { v1 = acc[e]; e1 = e; }
            float ex = expf(v1 - v0);
            float inv = 1.f / (1.f + ex);
            g_topk_idx[2 * t] = e0;  g_topk_idx[2 * t + 1] = e1;
            g_topk_w[2 * t] = inv;   g_topk_w[2 * t + 1] = ex * inv;
            atomicAdd(&g_cnt[e0], 1);
            atomicAdd(&g_cnt[e1], 1);
            atomicAdd(&g_top1[e0], 1);
            float s = 0.f; float pe[EE];
#pragma unroll
            for (int e = 0; e < EE; e++) { pe[e] = expf(acc[e] - v0); s += pe[e]; }
            float is = 1.f / s;
#pragma unroll
            for (int e = 0; e < EE; e++) psum[e] += pe[e] * is;
        }
    }
    if (lane == 0) {
        int wg = blockIdx.x * 8 + warp;
#pragma unroll
        for (int e = 0; e < EE; e++) g_prob_part[wg * EE + e] = psum[e];
    }
}

// ---------------- prep: aligned CSR offsets, tile table, aux loss ----------------
__global__ void prep_kernel(float* __restrict__ out, int out_size) {
    __shared__ float s_part[256];
    __shared__ float s_e[EE];
    int t = threadIdx.x;
    int e = t & 7, chunk = t >> 3;
    float s = 0.f;
    int w0 = chunk * 128;
    for (int w = w0; w < w0 + 128; w++) s += g_prob_part[w * EE + e];
    s_part[t] = s;
    __syncthreads();
    if (t < EE) {
        float tot = 0.f;
        for (int c = 0; c < 32; c++) tot += s_part[c * 8 + t];
        s_e[t] = tot;
    }
    __syncthreads();
    if (t == 0) {
        int o = 0, nt = 0;
        for (int ee = 0; ee < EE; ee++) {
            g_off[ee] = o;
            int cnt = g_cnt[ee];
            int ntl = (cnt + 127) >> 7;
            for (int i = 0; i < ntl; i++) {
                g_tile_e[nt] = ee;
                g_tile_base[nt] = o + i * 128;
                int v = cnt - i * 128;
                g_tile_valid[nt] = v > 128 ? 128 : v;
                nt++;
            }
            o += ntl * 128;
        }
        g_ntiles = nt;
        float aux = 0.f;
        const float invN = 1.f / (float)NTOK;
        for (int ee = 0; ee < EE; ee++)
            aux += (s_e[ee] * invN) * ((float)g_top1[ee] * invN);
        aux *= 0.01f * (float)EE;
        if (out_size > NTOK * DM) out[(size_t)NTOK * DM] = aux;
    }
}

// ---------------- fused scatter + pad (disjoint slot ranges) ----------------
__global__ void scatter_pad_kernel() {
    int b = blockIdx.x;
    if (b < NTOK / 256) {
        int t = b * 256 + threadIdx.x;
#pragma unroll
        for (int k = 0; k < 2; k++) {
            int e = g_topk_idx[2 * t + k];
            int p = atomicAdd(&g_cur[e], 1);
            int s = g_off[e] + p;
            g_list[s] = t;
            g_wl[s] = g_topk_w[2 * t + k];
        }
    } else {
        int s = (b - NTOK / 256) * 256 + threadIdx.x;
        if (s >= NKP_MAX) return;
        int e = EE - 1;
        for (int i = 1; i < EE; i++) if (s < g_off[i]) { e = i - 1; break; }
        if (s >= g_off[e] + g_cnt[e]) { g_list[s] = 0; g_wl[s] = 0.f; }
    }
}

// ---------------- fp16 warp-MMA grouped GEMM (cp.async 3-stage) ----------------
// CTA tile 128x256, BK=16, 256 threads = 8 warps (2x4), warp tile 64x64.
// Preconverted half2 sources; loads land in SMEM via cp.async (no staging/STS).
// SMEM (half2 words): A [m][kword] stride 12; B [kpair][n] stride 264.
#define ASTRW 12
#define BSTRW 264
#define A_STW (128 * ASTRW)   // 1536 words / stage
#define B_STW (8 * BSTRW)     // 2112 words / stage

template<int PHASE>
__global__ __launch_bounds__(256, 1) void moe_mma(
        const float* __restrict__ bias_all,
        float* __restrict__ out) {
    constexpr int KD  = (PHASE == 1) ? DM : FF;   // reduction dim
    constexpr int ND  = (PHASE == 1) ? FF : DM;   // output dim
    constexpr int NIT = KD / 16;

    int tile = blockIdx.y;
    if (tile >= g_ntiles) return;
    int e     = g_tile_e[tile];
    int base  = g_tile_base[tile];
    int valid = g_tile_valid[tile];
    int nb    = blockIdx.x * 256;

    __shared__ uint32_t sA[3][A_STW];
    __shared__ uint32_t sB[3][B_STW];

    int t = threadIdx.x;
    int wid = t >> 5, lane = t & 31;
    int g  = lane >> 2;          // 0..7
    int tg = lane & 3;           // 0..3
    int warp_m = (wid >> 2) * 64;
    int warp_n = (wid & 3) * 64;

    // A loader: row r = t&127, word offset aoff = (t>>7)*4 (one 16B unit/iter)
    int r    = t & 127;
    int aoff = (t >> 7) * 4;
    const uint32_t* arowW;
    if (PHASE == 1) {
        int tok = g_list[base + r];
        arowW = (const uint32_t*)(g_xh + (size_t)tok * DM);
    } else {
        arowW = (const uint32_t*)(g_Hh + (size_t)(base + r) * FF);
    }
    // B loader: n word block bn0 = (t&63)*4; kpairs kp0 and kp0+4
    int bn0 = (t & 63) * 4;
    int kp0 = t >> 6;
    const uint32_t* Bi = ((PHASE == 1) ? g_w1i : g_w2i)
                         + (size_t)e * (KD / 2) * ND + nb;  // word units

    uint32_t aw[3], bw0[3], bw1[3];
#pragma unroll
    for (int st = 0; st < 3; st++) {
        aw[st]  = (uint32_t)__cvta_generic_to_shared(&sA[st][r * ASTRW + aoff]);
        bw0[st] = (uint32_t)__cvta_generic_to_shared(&sB[st][kp0 * BSTRW + bn0]);
        bw1[st] = (uint32_t)__cvta_generic_to_shared(&sB[st][(kp0 + 4) * BSTRW + bn0]);
    }

    float acc[4][8][4];
#pragma unroll
    for (int mt = 0; mt < 4; mt++)
#pragma unroll
        for (int nt = 0; nt < 8; nt++)
#pragma unroll
            for (int i = 0; i < 4; i++) acc[mt][nt][i] = 0.f;

    // prologue: issue chunks 0 and 1
#pragma unroll
    for (int c = 0; c < 2; c++) {
        int kwp = c * 8;   // word offset / kpair base of chunk c
        cp16(aw[c], arowW + kwp + aoff);
        cp16(bw0[c], Bi + (size_t)(kwp + kp0) * ND + bn0);
        cp16(bw1[c], Bi + (size_t)(kwp + kp0 + 4) * ND + bn0);
        CP_COMMIT();
    }

    int s = 0;
    for (int it = 0; it < NIT; it++) {
        if (it + 1 < NIT) CP_WAIT1(); else CP_WAIT0();
        __syncthreads();
        // compute one k16 step from stage s
        {
            const uint32_t* As = sA[s];
            const uint32_t* Bs = sB[s];
            uint32_t af[4][4], bf[8][2];
#pragma unroll
            for (int mt = 0; mt < 4; mt++) {
                int m0 = warp_m + mt * 16 + g;
                af[mt][0] = As[m0 * ASTRW + tg];
                af[mt][1] = As[(m0 + 8) * ASTRW + tg];
                af[mt][2] = As[m0 * ASTRW + 4 + tg];
                af[mt][3] = As[(m0 + 8) * ASTRW + 4 + tg];
            }
#pragma unroll
            for (int nt = 0; nt < 8; nt++) {
                int n0 = warp_n + nt * 8 + g;
                bf[nt][0] = Bs[tg * BSTRW + n0];
                bf[nt][1] = Bs[(4 + tg) * BSTRW + n0];
            }
#pragma unroll
            for (int mt = 0; mt < 4; mt++)
#pragma unroll
                for (int nt = 0; nt < 8; nt++)
                    mma_f16(acc[mt][nt], af[mt], bf[nt]);
        }
        // issue chunk it+2 into stage (s+2)%3; that stage's old chunk (it-1)
        // finished compute at iter it-1, fenced by this iter's __syncthreads.
        int nx = it + 2;
        if (nx < NIT) {
            int sn = s + 2; if (sn >= 3) sn -= 3;
            int kwp = nx * 8;
            cp16(aw[sn], arowW + kwp + aoff);
            cp16(bw0[sn], Bi + (size_t)(kwp + kp0) * ND + bn0);
            cp16(bw1[sn], Bi + (size_t)(kwp + kp0 + 4) * ND + bn0);
            CP_COMMIT();
        }
        if (++s == 3) s = 0;
    }

    // ---------------- epilogue ----------------
    // Fragment D mapping: c0:(row=g, col=tg*2) c1:(col+1) c2:(row+8) c3:(row+8,col+1)
    const float* bvec = bias_all + (size_t)e * ND + nb;
    if (PHASE == 1) {
#pragma unroll
        for (int mt = 0; mt < 4; mt++) {
            int rr0 = warp_m + mt * 16 + g;
            __half* H0 = g_Hh + (size_t)(base + rr0) * FF + nb;
            __half* H1 = g_Hh + (size_t)(base + rr0 + 8) * FF + nb;
#pragma unroll
            for (int nt = 0; nt < 8; nt++) {
                int c = warp_n + nt * 8 + tg * 2;
                float b0 = bvec[c], b1 = bvec[c + 1];
                *(uint32_t*)(H0 + c) = pack_h2(gelu_exact(acc[mt][nt][0] + b0),
                                               gelu_exact(acc[mt][nt][1] + b1));
                *(uint32_t*)(H1 + c) = pack_h2(gelu_exact(acc[mt][nt][2] + b0),
                                               gelu_exact(acc[mt][nt][3] + b1));
            }
        }
    } else {
#pragma unroll
        for (int mt = 0; mt < 4; mt++) {
            int rr0 = warp_m + mt * 16 + g;
#pragma unroll
            for (int half = 0; half < 2; half++) {
                int rr = rr0 + half * 8;
                if (rr < valid) {
                    int slot = base + rr;
                    int tok  = g_list[slot];
                    float gw = g_wl[slot];
                    float* O = out + (size_t)tok * DM + nb;
#pragma unroll
                    for (int nt = 0; nt < 8; nt++) {
                        int c = warp_n + nt * 8 + tg * 2;
                        red_add_v2(O + c,
                                   gw * (acc[mt][nt][half * 2]     + bvec[c]),
                                   gw * (acc[mt][nt][half * 2 + 1] + bvec[c + 1]));
                    }
                }
            }
        }
    }
}

// ---------------- launch ----------------
extern "C" void kernel_launch(void* const* d_in, const int* in_sizes, int n_in,
                              void* d_out, int out_size) {
    const float* x  = (const float*)d_in[0];
    const float* rw = (const float*)d_in[1];
    const float* w1 = (const float*)d_in[2];
    const float* b1 = (const float*)d_in[3];
    const float* w2 = (const float*)d_in[4];
    const float* b2 = (const float*)d_in[5];
    float* out = (float*)d_out;

    cudaMemsetAsync(out, 0, (size_t)NTOK * DM * sizeof(float), 0);
    conv_w_all<<<W1BLK + W2BLK, 256>>>(w1, w2);     // also zeroes counters (block 0)
    router_kernel<<<RBLK, 256>>>(x, rw);            // also writes fp16 x image
    prep_kernel<<<1, 256>>>(out, out_size);
    scatter_pad_kernel<<<NTOK / 256 + NKP_MAX / 256, 256>>>();
    moe_mma<1><<<dim3(FF / 256, MAX_TILES), 256>>>(b1, out);
    moe_mma<2><<<dim3(DM / 256, MAX_TILES), 256>>>(b2, out);
}